// round 13
// baseline (speedup 1.0000x reference)
#include <cuda_runtime.h>
#include <cuda_bf16.h>
#include <math.h>
#include <stdint.h>

#define HW_   8064          // 64*126
#define HWP_  8192          // padded spatial: 64*128
#define BC_   8192          // 128*64
#define NMODE 4096          // 64*64

typedef __nv_bfloat16 bf16;
typedef unsigned int u32;

// ---------------- device scratch ----------------
__device__ __align__(16) bf16 P0h[BC_ * (size_t)HWP_];
__device__ __align__(16) bf16 P0l[BC_ * (size_t)HWP_];
__device__ __align__(16) u32  g_p1[BC_ * (size_t)8192];      // bc-major packed
__device__ __align__(16) u32  g_p2[NMODE * (size_t)16384];   // mode-major packed
__device__ __align__(16) u32  g_p3[NMODE * (size_t)16384];   // mode-major packed
__device__ __align__(16) bf16 WTh[NMODE * (size_t)4096];
__device__ __align__(16) bf16 WTl[NMODE * (size_t)4096];
__device__ __align__(16) bf16 BWh[16384],  BWl[16384];    // fwd width  [w][n]
__device__ __align__(16) bf16 BIh[16384],  BIl[16384];    // inv width  [n][w]
__device__ __align__(16) bf16 BGh[16384],  BGl[16384];    // fwd height [m][j]
__device__ __align__(16) bf16 BG2h[16384], BG2l[16384];   // inv height [m][j]
__device__ float g_mw[4096];

// ---------------- helpers ----------------
__device__ __forceinline__ void splitf(float v, bf16& h, bf16& l) {
    h = __float2bfloat16(v);
    l = __float2bfloat16(v - __bfloat162float(h));
}
__device__ __forceinline__ u32 pack_split(float v) {
    bf16 h, l; splitf(v, h, l);
    return (u32)__bfloat16_as_ushort(h) | ((u32)__bfloat16_as_ushort(l) << 16);
}
__device__ __forceinline__ void split_store2(bf16* H, bf16* L, size_t off, float a, float b) {
    bf16 ha, la, hb, lb; splitf(a, ha, la); splitf(b, hb, lb);
    *(__nv_bfloat162*)(H + off) = __halves2bfloat162(ha, hb);
    *(__nv_bfloat162*)(L + off) = __halves2bfloat162(la, lb);
}
__device__ __forceinline__ u32 prmtf(u32 a, u32 b, u32 s) {
    u32 d; asm("prmt.b32 %0,%1,%2,%3;" : "=r"(d) : "r"(a), "r"(b), "r"(s)); return d;
}
__device__ __forceinline__ float gelu_f(float v) {
    return 0.5f * v * (1.0f + erff(v * 0.70710678118654752f));
}

// ---------------- basis precompute (split planes) ----------------
__global__ void k_basis(const float* __restrict__ mwin) {
    int i = blockIdx.x * blockDim.x + threadIdx.x;
    const double PI2 = 6.283185307179586476925286766559;
    if (i < 16384) {
        int r = i >> 7, c = i & 127;
        float v = 0.f;
        if (r < 126) {
            int k = c & 63;
            double th = PI2 * (double)(k * r) / 126.0;
            v = (c < 64) ? (float)cos(th) : (float)(-sin(th));
        }
        splitf(v, BWh[i], BWl[i]);
        float v2 = 0.f;
        if (c < 126) {
            int k = r & 63;
            double a = (k == 0 || k == 63) ? (1.0 / 126.0) : (2.0 / 126.0);
            double th = PI2 * (double)(k * c) / 126.0;
            v2 = (r < 64) ? (float)(a * cos(th)) : (float)(-a * sin(th));
        }
        splitf(v2, BIh[i], BIl[i]);
        {
            int ky = r & 63, h = c & 63;
            double th = PI2 * (double)(ky * h) / 64.0;
            double cs = cos(th), sn = sin(th);
            float g = (float)((r < 64) ? ((c < 64) ? cs : sn) : ((c < 64) ? -sn : cs));
            splitf(g, BGh[i], BGl[i]);
        }
        {
            int h = r & 63, ky = c & 63;
            double th = PI2 * (double)(ky * h) / 64.0;
            double cs = cos(th) / 64.0, sn = sin(th) / 64.0;
            float g = (float)((r < 64) ? ((c < 64) ? cs : -sn) : ((c < 64) ? sn : cs));
            splitf(g, BG2h[i], BG2l[i]);
        }
    }
    if (i < 4096) {
        int ky = i >> 6, kx = i & 63;
        float s1 = 1.f / (1.f + expf(-mwin[i]));
        if (kx == 0 || kx == 63) {
            float s2 = 1.f / (1.f + expf(-mwin[(((64 - ky) & 63) << 6) + kx]));
            s1 = 0.5f * (s1 + s2);
        }
        g_mw[i] = s1;
    }
}

// ---------------- encoder 1x1 conv 3 -> 64 ----------------
__global__ __launch_bounds__(256) void k_enc(const float* __restrict__ xin,
                                             const float* __restrict__ ew,
                                             const float* __restrict__ eb) {
    __shared__ float sx[3 * 126];
    __shared__ float sw[192];
    __shared__ float sb[64];
    int b = blockIdx.x >> 6, h = blockIdx.x & 63;
    int t = threadIdx.x;
    if (t < 192) sw[t] = ew[t];
    if (t < 64)  sb[t] = eb[t];
    for (int idx = t; idx < 378; idx += 256) {
        int j = idx / 126, w = idx % 126;
        sx[idx] = xin[(size_t)(b * 3 + j) * HW_ + h * 126 + w];
    }
    __syncthreads();
    for (int idx = t; idx < 64 * 126; idx += 256) {
        int c = idx / 126, w = idx % 126;
        float v = sb[c] + sw[c * 3] * sx[w] + sw[c * 3 + 1] * sx[126 + w]
                        + sw[c * 3 + 2] * sx[252 + w];
        size_t off = (size_t)(b * 64 + c) * HWP_ + h * 128 + w;
        splitf(v, P0h[off], P0l[off]);
    }
}

// ======================================================================
// mma core: warp tile 32x32, split-bf16 (3 MMAs)
// ======================================================================
#define LDSM4(R0,R1,R2,R3,ADDR)                                              \
    asm volatile("ldmatrix.sync.aligned.m8n8.x4.shared.b16 {%0,%1,%2,%3}, [%4];" \
        : "=r"(R0),"=r"(R1),"=r"(R2),"=r"(R3) : "r"(ADDR))
#define LDSM4T(R0,R1,R2,R3,ADDR)                                             \
    asm volatile("ldmatrix.sync.aligned.m8n8.x4.trans.shared.b16 {%0,%1,%2,%3}, [%4];" \
        : "=r"(R0),"=r"(R1),"=r"(R2),"=r"(R3) : "r"(ADDR))
#define MMA16816(D,A,B)                                                      \
    asm volatile("mma.sync.aligned.m16n8k16.row.col.f32.bf16.bf16.f32 "      \
        "{%0,%1,%2,%3}, {%4,%5,%6,%7}, {%8,%9}, {%0,%1,%2,%3};"              \
        : "+f"((D)[0]),"+f"((D)[1]),"+f"((D)[2]),"+f"((D)[3])                \
        : "r"((A)[0]),"r"((A)[1]),"r"((A)[2]),"r"((A)[3]),                   \
          "r"((B)[0]),"r"((B)[1]))

template<int SA, int SB, int KSTEPS>
__device__ __forceinline__ void mma_core(
    const bf16* Ah, const bf16* Al, const bf16* Bh, const bf16* Bl,
    int m0w, int n0w, int lane, float (&acc)[2][4][4])
{
    unsigned baAh = (unsigned)__cvta_generic_to_shared(Ah);
    unsigned baAl = (unsigned)__cvta_generic_to_shared(Al);
    unsigned baBh = (unsigned)__cvta_generic_to_shared(Bh);
    unsigned baBl = (unsigned)__cvta_generic_to_shared(Bl);
    int aRow = m0w + (lane & 15);
    int aCol = (lane >> 4) << 3;
    int bRow = lane & 15;
    int bCol = n0w + ((lane >> 4) << 3);
#pragma unroll
    for (int ks = 0; ks < KSTEPS; ks++) {
        uint32_t ah[2][4], al[2][4], bh[4][2], bl[4][2];
#pragma unroll
        for (int mt = 0; mt < 2; mt++) {
            unsigned offA = (unsigned)((aRow + mt * 16) * SA + ks * 16 + aCol) * 2u;
            LDSM4(ah[mt][0], ah[mt][1], ah[mt][2], ah[mt][3], baAh + offA);
            LDSM4(al[mt][0], al[mt][1], al[mt][2], al[mt][3], baAl + offA);
        }
#pragma unroll
        for (int np = 0; np < 2; np++) {
            unsigned offB = (unsigned)((ks * 16 + bRow) * SB + bCol + np * 16) * 2u;
            LDSM4T(bh[2*np][0], bh[2*np][1], bh[2*np+1][0], bh[2*np+1][1], baBh + offB);
            LDSM4T(bl[2*np][0], bl[2*np][1], bl[2*np+1][0], bl[2*np+1][1], baBl + offB);
        }
#pragma unroll
        for (int mt = 0; mt < 2; mt++)
#pragma unroll
            for (int nt = 0; nt < 4; nt++) {
                MMA16816(acc[mt][nt], ah[mt], bh[nt]);
                MMA16816(acc[mt][nt], ah[mt], bl[nt]);
                MMA16816(acc[mt][nt], al[mt], bh[nt]);
            }
    }
}

#define SMEM_MAT (128 * 136)
#define RACC _Pragma("unroll") for (int a_ = 0; a_ < 2; a_++)                \
    _Pragma("unroll") for (int b_ = 0; b_ < 4; b_++)                         \
    _Pragma("unroll") for (int c_ = 0; c_ < 4; c_++) acc[a_][b_][c_] = 0.f;

// ======================================================================
// FUSED forward: widthDFT -> (smem transpose) -> heightDFT*mw -> g_p1
// CTA = 2 bc. MMA1: C1[(bc,h)][(ri,kx)] = P0 * BW. Transpose to
// B2[(ri,h)][(bc,kx)], MMA2: C2[(ri,ky)][(bc,kx)] = BG * B2.
// ======================================================================
__global__ __launch_bounds__(512) void k_fwd_fused() {
    extern __shared__ __align__(16) char smraw[];
    bf16* Ah = (bf16*)smraw;
    bf16* Al = Ah + SMEM_MAT;
    bf16* Bh = Al + SMEM_MAT;
    bf16* Bl = Bh + SMEM_MAT;
    int t = threadIdx.x, lane = t & 31, warp = t >> 5;
    int m0w = (warp >> 2) * 32, n0w = (warp & 3) * 32;
    int rb = m0w + (lane >> 2), cb = n0w + (lane & 3) * 2;
    int bcBase = blockIdx.x * 2;

    // phase 1 staging: A = P0 (2 bc), B = BW
    const uint4* sAh = (const uint4*)(P0h + (size_t)blockIdx.x * 16384);
    const uint4* sAl = (const uint4*)(P0l + (size_t)blockIdx.x * 16384);
    const uint4* sBh = (const uint4*)BWh;
    const uint4* sBl = (const uint4*)BWl;
    for (int idx = t; idx < 2048; idx += 512) {
        int r = idx >> 4, c = idx & 15;
        *(uint4*)(Ah + r * 136 + c * 8) = sAh[idx];
        *(uint4*)(Al + r * 136 + c * 8) = sAl[idx];
        *(uint4*)(Bh + r * 136 + c * 8) = sBh[idx];
        *(uint4*)(Bl + r * 136 + c * 8) = sBl[idx];
    }
    __syncthreads();
    float acc[2][4][4];
    RACC
    mma_core<136, 136, 8>(Ah, Al, Bh, Bl, m0w, n0w, lane, acc);
    __syncthreads();

    // restage: A <- BG planes ; B <- transpose(C1) split
    const uint4* gAh = (const uint4*)BGh;
    const uint4* gAl = (const uint4*)BGl;
    for (int idx = t; idx < 2048; idx += 512) {
        int r = idx >> 4, c = idx & 15;
        *(uint4*)(Ah + r * 136 + c * 8) = gAh[idx];
        *(uint4*)(Al + r * 136 + c * 8) = gAl[idx];
    }
#pragma unroll
    for (int mt = 0; mt < 2; mt++)
#pragma unroll
        for (int nt = 0; nt < 4; nt++) {
            int col = cb + nt * 8;
            int jc = (col >> 6) * 64, c2b = col & 63;
            int r0 = rb + mt * 16, r1 = r0 + 8;
            int j0 = jc + (r0 & 63), c20 = (r0 >> 6) * 64 + c2b;
            int j1 = jc + (r1 & 63), c21 = (r1 >> 6) * 64 + c2b;
            split_store2(Bh, Bl, (size_t)j0 * 136 + c20, acc[mt][nt][0], acc[mt][nt][1]);
            split_store2(Bh, Bl, (size_t)j1 * 136 + c21, acc[mt][nt][2], acc[mt][nt][3]);
        }
    __syncthreads();
    RACC
    mma_core<136, 136, 8>(Ah, Al, Bh, Bl, m0w, n0w, lane, acc);

    // epilogue: rows m=(ri,ky), cols (bc,kx); *mw; pack to g_p1
    int rb2 = rb, cb2 = cb;
#pragma unroll
    for (int mt = 0; mt < 2; mt++)
#pragma unroll
        for (int nt = 0; nt < 4; nt++) {
            int col = cb2 + nt * 8;
            int bc = bcBase + (col >> 6), kx = col & 63;
            int r0 = rb2 + mt * 16, r1 = r0 + 8;
            float2 w0 = *(const float2*)(g_mw + (r0 & 63) * 64 + kx);
            float2 w1 = *(const float2*)(g_mw + (r1 & 63) * 64 + kx);
            *(uint2*)(g_p1 + (size_t)bc * 8192 + r0 * 64 + kx) =
                make_uint2(pack_split(acc[mt][nt][0] * w0.x), pack_split(acc[mt][nt][1] * w0.y));
            *(uint2*)(g_p1 + (size_t)bc * 8192 + r1 * 64 + kx) =
                make_uint2(pack_split(acc[mt][nt][2] * w1.x), pack_split(acc[mt][nt][3] * w1.y));
        }
}

// ======================================================================
// FUSED inverse: heightIDFT -> (smem transpose) -> widthIDFT+bias+GELU -> P0
// CTA = 2 bc. MMA1: C2[(ri2,h)][(bc,kx)] = BG2 * B1(g_p1). Transpose to
// A2[(bc,h)][(ri2,kx)], MMA2: C3[(bc,h)][w] = A2 * BI.
// ======================================================================
__global__ __launch_bounds__(512) void k_inv_fused(const float* __restrict__ sb,
                                                   const float* __restrict__ mb_) {
    extern __shared__ __align__(16) char smraw[];
    bf16* Ah = (bf16*)smraw;
    bf16* Al = Ah + SMEM_MAT;
    bf16* Bh = Al + SMEM_MAT;
    bf16* Bl = Bh + SMEM_MAT;
    int t = threadIdx.x, lane = t & 31, warp = t >> 5;
    int m0w = (warp >> 2) * 32, n0w = (warp & 3) * 32;
    int rb = m0w + (lane >> 2), cb = n0w + (lane & 3) * 2;
    int bcBase = blockIdx.x * 2;

    // phase 1 staging: A = BG2 planes; B = unpack g_p1
    const uint4* gAh = (const uint4*)BG2h;
    const uint4* gAl = (const uint4*)BG2l;
    for (int idx = t; idx < 2048; idx += 512) {
        int r = idx >> 4, c = idx & 15;
        *(uint4*)(Ah + r * 136 + c * 8) = gAh[idx];
        *(uint4*)(Al + r * 136 + c * 8) = gAl[idx];
    }
    for (int idx = t; idx < 8192; idx += 512) {
        int r = idx >> 6, pc = idx & 63;
        int col0 = pc * 2;
        uint2 p = *(const uint2*)(g_p1 + (size_t)(bcBase + (col0 >> 6)) * 8192
                                  + r * 64 + (col0 & 63));
        *(u32*)(Bh + r * 136 + col0) = prmtf(p.x, p.y, 0x5410);
        *(u32*)(Bl + r * 136 + col0) = prmtf(p.x, p.y, 0x7632);
    }
    __syncthreads();
    float acc[2][4][4];
    RACC
    mma_core<136, 136, 8>(Ah, Al, Bh, Bl, m0w, n0w, lane, acc);
    __syncthreads();

    // restage: A <- transpose(C2) split ; B <- BI planes
    const uint4* sBh = (const uint4*)BIh;
    const uint4* sBl = (const uint4*)BIl;
    for (int idx = t; idx < 2048; idx += 512) {
        int r = idx >> 4, c = idx & 15;
        *(uint4*)(Bh + r * 136 + c * 8) = sBh[idx];
        *(uint4*)(Bl + r * 136 + c * 8) = sBl[idx];
    }
#pragma unroll
    for (int mt = 0; mt < 2; mt++)
#pragma unroll
        for (int nt = 0; nt < 4; nt++) {
            int col = cb + nt * 8;
            int rowc = (col >> 6) * 64, c2b = col & 63;
            int r0 = rb + mt * 16, r1 = r0 + 8;
            int a0 = rowc + (r0 & 63), c20 = (r0 >> 6) * 64 + c2b;
            int a1 = rowc + (r1 & 63), c21 = (r1 >> 6) * 64 + c2b;
            split_store2(Ah, Al, (size_t)a0 * 136 + c20, acc[mt][nt][0], acc[mt][nt][1]);
            split_store2(Ah, Al, (size_t)a1 * 136 + c21, acc[mt][nt][2], acc[mt][nt][3]);
        }
    __syncthreads();
    RACC
    mma_core<136, 136, 8>(Ah, Al, Bh, Bl, m0w, n0w, lane, acc);

    // epilogue: rows (bc,h), cols w; bias + exact GELU -> P0 planes
#pragma unroll
    for (int mt = 0; mt < 2; mt++)
#pragma unroll
        for (int nt = 0; nt < 4; nt++) {
            int col = cb + nt * 8;
            if (col >= 126) continue;
            int r0 = rb + mt * 16, r1 = r0 + 8;
            int bc0 = bcBase + (r0 >> 6), h0 = r0 & 63;
            int bc1 = bcBase + (r1 >> 6), h1 = r1 & 63;
            float bias0 = __ldg(sb + (bc0 & 63)) + __ldg(mb_ + (bc0 & 63));
            float bias1 = __ldg(sb + (bc1 & 63)) + __ldg(mb_ + (bc1 & 63));
            split_store2(P0h, P0l, (size_t)bc0 * HWP_ + h0 * 128 + col,
                         gelu_f(acc[mt][nt][0] + bias0), gelu_f(acc[mt][nt][1] + bias0));
            split_store2(P0h, P0l, (size_t)bc1 * HWP_ + h1 * 128 + col,
                         gelu_f(acc[mt][nt][2] + bias1), gelu_f(acc[mt][nt][3] + bias1));
        }
}

// ---------------- transpose to mode-major (packed u32) ----------------
__global__ __launch_bounds__(256) void k_t1() {
    __shared__ u32 s[128 * 65];
    int b = blockIdx.x >> 6, ky = blockIdx.x & 63;
    int t = threadIdx.x;
    for (int idx = t; idx < 8192; idx += 256) {
        int i = idx >> 7, r = idx & 127, ri = r >> 6, kx = r & 63;
        s[(ri * 64 + i) * 65 + kx] =
            g_p1[(size_t)(b * 64 + i) * 8192 + ri * 4096 + ky * 64 + kx];
    }
    __syncthreads();
    for (int idx = t; idx < 8192; idx += 256) {
        int kx = idx >> 7, c = idx & 127;
        g_p2[(size_t)(ky * 64 + kx) * 16384 + b * 128 + c] = s[c * 65 + kx];
    }
}

// ---------------- transpose back from mode-major (packed u32) ----------------
__global__ __launch_bounds__(256) void k_t2() {
    __shared__ u32 s[128 * 65];
    int b = blockIdx.x >> 6, ky = blockIdx.x & 63;
    int t = threadIdx.x;
    for (int idx = t; idx < 8192; idx += 256) {
        int kx = idx >> 7, c = idx & 127;
        s[c * 65 + kx] = g_p3[(size_t)(ky * 64 + kx) * 16384 + b * 128 + c];
    }
    __syncthreads();
    for (int idx = t; idx < 8192; idx += 256) {
        int o = idx >> 7, r = idx & 127, ri = r >> 6, kx = r & 63;
        g_p1[(size_t)(b * 64 + o) * 8192 + ri * 4096 + ky * 64 + kx] =
            s[(ri * 64 + o) * 65 + kx];
    }
}

// ---------------- weight fold (writes split planes) ----------------
__global__ void k_wt(const float* __restrict__ spec, const float* __restrict__ mlp) {
    __shared__ float tile[32][33];
    int x = blockIdx.x * 32 + threadIdx.x;   // mode
    int yb = blockIdx.y * 32;                // io
#pragma unroll
    for (int j = 0; j < 32; j += 8)
        tile[threadIdx.y + j][threadIdx.x] = spec[(size_t)(yb + threadIdx.y + j) * 4096 + x];
    __syncthreads();
    int io2 = yb + threadIdx.x;
    float madd = mlp[(io2 & 63) * 64 + (io2 >> 6)];
    int mb = blockIdx.x * 32;
#pragma unroll
    for (int j = 0; j < 32; j += 8) {
        float v = tile[threadIdx.x][threadIdx.y + j] + madd;
        size_t off = (size_t)(mb + threadIdx.y + j) * 4096 + io2;
        splitf(v, WTh[off], WTl[off]);
    }
}

// ======================================================================
// per-mode GEMM: C[256 x 64] = X[256 x 64] W[64 x 64], K=64
// ======================================================================
__global__ __launch_bounds__(512) void k_sgemm() {
    extern __shared__ __align__(16) char smraw[];
    bf16* Ah = (bf16*)smraw;            // [256][72]
    bf16* Al = Ah + 256 * 72;
    bf16* Bh = Al + 256 * 72;           // [64][72]
    bf16* Bl = Bh + 64 * 72;
    int t = threadIdx.x, lane = t & 31, warp = t >> 5;
    int mode = blockIdx.x;
    const u32* asrc = g_p2 + (size_t)mode * 16384;
    for (int idx = t; idx < 8192; idx += 512) {
        int r = idx >> 5, pc = idx & 31;
        int col0 = pc * 2;
        uint2 p = *(const uint2*)(asrc + r * 64 + col0);
        *(u32*)(Ah + r * 72 + col0) = prmtf(p.x, p.y, 0x5410);
        *(u32*)(Al + r * 72 + col0) = prmtf(p.x, p.y, 0x7632);
    }
    const uint4* sBh = (const uint4*)(WTh + (size_t)mode * 4096);
    const uint4* sBl = (const uint4*)(WTl + (size_t)mode * 4096);
    for (int idx = t; idx < 512; idx += 512) {
        int r = idx >> 3, c = idx & 7;
        *(uint4*)(Bh + r * 72 + c * 8) = sBh[idx];
        *(uint4*)(Bl + r * 72 + c * 8) = sBl[idx];
    }
    __syncthreads();
    int m0w = (warp >> 1) * 32, n0w = (warp & 1) * 32;
    float acc[2][4][4];
    RACC
    mma_core<72, 72, 4>(Ah, Al, Bh, Bl, m0w, n0w, lane, acc);
    int rb = m0w + (lane >> 2), cb = n0w + (lane & 3) * 2;
    u32* dst = g_p3 + (size_t)mode * 16384;
#pragma unroll
    for (int mt = 0; mt < 2; mt++)
#pragma unroll
        for (int nt = 0; nt < 4; nt++) {
            int col = cb + nt * 8;
            int r0 = rb + mt * 16, r1 = r0 + 8;
            *(uint2*)(dst + r0 * 64 + col) =
                make_uint2(pack_split(acc[mt][nt][0]), pack_split(acc[mt][nt][1]));
            *(uint2*)(dst + r1 * 64 + col) =
                make_uint2(pack_split(acc[mt][nt][2]), pack_split(acc[mt][nt][3]));
        }
}

// ---------------- decoder 1x1 conv 64 -> 1 ----------------
__global__ __launch_bounds__(256) void k_dec(const float* __restrict__ dw,
                                             const float* __restrict__ db,
                                             float* __restrict__ out) {
    __shared__ float sw[64];
    int b = blockIdx.x, t = threadIdx.x;
    if (t < 64) sw[t] = dw[t];
    __syncthreads();
    float bias = __ldg(db);
    for (int p = t; p < HWP_; p += 256) {
        int w = p & 127;
        if (w >= 126) continue;
        int h = p >> 7;
        float s = bias;
        size_t base = (size_t)b * 64 * HWP_ + p;
#pragma unroll 8
        for (int c = 0; c < 64; c++) {
            size_t off = base + (size_t)c * HWP_;
            s = fmaf(sw[c], __bfloat162float(P0h[off]) + __bfloat162float(P0l[off]), s);
        }
        out[(size_t)b * HW_ + h * 126 + w] = s;
    }
}

extern "C" void kernel_launch(void* const* d_in, const int* in_sizes, int n_in,
                              void* d_out, int out_size) {
    const float* x       = (const float*)d_in[0];
    const float* mode_w  = (const float*)d_in[1];
    const float* enc_w   = (const float*)d_in[2];
    const float* enc_b   = (const float*)d_in[3];
    const float* dec_w   = (const float*)d_in[4];
    const float* dec_b   = (const float*)d_in[5];
    const float* spec_w  = (const float*)d_in[6];
    const float* spec_b  = (const float*)d_in[7];
    const float* mlp_w   = (const float*)d_in[8];
    const float* mlp_b   = (const float*)d_in[9];
    float* out = (float*)d_out;

    const int smemBig = 4 * SMEM_MAT * 2;                     // 139,264 B
    const int smemS   = (2 * 256 * 72 + 2 * 64 * 72) * 2;     //  92,160 B
    cudaFuncSetAttribute(k_fwd_fused, cudaFuncAttributeMaxDynamicSharedMemorySize, smemBig);
    cudaFuncSetAttribute(k_inv_fused, cudaFuncAttributeMaxDynamicSharedMemorySize, smemBig);
    cudaFuncSetAttribute(k_sgemm,     cudaFuncAttributeMaxDynamicSharedMemorySize, smemS);

    k_basis<<<64, 256>>>(mode_w);
    k_enc<<<8192, 256>>>(x, enc_w, enc_b);

    for (int l = 0; l < 4; l++) {
        k_wt<<<dim3(128, 128), dim3(32, 8)>>>(spec_w + (size_t)l * 16777216,
                                              mlp_w + (size_t)l * 4096);
        k_fwd_fused<<<4096, 512, smemBig>>>();
        k_t1<<<8192, 256>>>();
        k_sgemm<<<4096, 512, smemS>>>();
        k_t2<<<8192, 256>>>();
        k_inv_fused<<<4096, 512, smemBig>>>(spec_b + l * 64, mlp_b + l * 64);
    }
    k_dec<<<128, 256>>>(dec_w, dec_b, out);
}

// round 14
// speedup vs baseline: 1.0158x; 1.0158x over previous
#include <cuda_runtime.h>
#include <cuda_bf16.h>
#include <math.h>
#include <stdint.h>

#define HW_   8064          // 64*126
#define HWP_  8192          // padded spatial: 64*128
#define BC_   8192          // 128*64
#define NMODE 4096          // 64*64

typedef __nv_bfloat16 bf16;
typedef unsigned int u32;

// ---------------- device scratch ----------------
__device__ __align__(16) bf16 P0h[BC_ * (size_t)HWP_];
__device__ __align__(16) bf16 P0l[BC_ * (size_t)HWP_];
__device__ __align__(16) u32  g_p1[BC_ * (size_t)8192];      // bc-major packed
__device__ __align__(16) u32  g_p2[NMODE * (size_t)16384];   // mode-major packed
__device__ __align__(16) u32  g_p3[NMODE * (size_t)16384];   // mode-major packed
__device__ __align__(16) bf16 WTh[NMODE * (size_t)4096];
__device__ __align__(16) bf16 WTl[NMODE * (size_t)4096];
__device__ __align__(16) bf16 BWh[16384],  BWl[16384];    // fwd width  [w][n]
__device__ __align__(16) bf16 BIh[16384],  BIl[16384];    // inv width  [n][w]
__device__ __align__(16) bf16 BGh[16384],  BGl[16384];    // fwd height [m][j]
__device__ __align__(16) bf16 BG2h[16384], BG2l[16384];   // inv height [m][j]
__device__ float g_mw[4096];

// ---------------- helpers ----------------
__device__ __forceinline__ void splitf(float v, bf16& h, bf16& l) {
    h = __float2bfloat16(v);
    l = __float2bfloat16(v - __bfloat162float(h));
}
__device__ __forceinline__ u32 pack_split(float v) {
    bf16 h, l; splitf(v, h, l);
    return (u32)__bfloat16_as_ushort(h) | ((u32)__bfloat16_as_ushort(l) << 16);
}
__device__ __forceinline__ void split_store2(bf16* H, bf16* L, size_t off, float a, float b) {
    bf16 ha, la, hb, lb; splitf(a, ha, la); splitf(b, hb, lb);
    *(__nv_bfloat162*)(H + off) = __halves2bfloat162(ha, hb);
    *(__nv_bfloat162*)(L + off) = __halves2bfloat162(la, lb);
}
__device__ __forceinline__ u32 prmtf(u32 a, u32 b, u32 s) {
    u32 d; asm("prmt.b32 %0,%1,%2,%3;" : "=r"(d) : "r"(a), "r"(b), "r"(s)); return d;
}
__device__ __forceinline__ float gelu_f(float v) {
    return 0.5f * v * (1.0f + erff(v * 0.70710678118654752f));
}

// ---------------- basis precompute (split planes) ----------------
__global__ void k_basis(const float* __restrict__ mwin) {
    int i = blockIdx.x * blockDim.x + threadIdx.x;
    const double PI2 = 6.283185307179586476925286766559;
    if (i < 16384) {
        int r = i >> 7, c = i & 127;
        float v = 0.f;
        if (r < 126) {
            int k = c & 63;
            double th = PI2 * (double)(k * r) / 126.0;
            v = (c < 64) ? (float)cos(th) : (float)(-sin(th));
        }
        splitf(v, BWh[i], BWl[i]);
        float v2 = 0.f;
        if (c < 126) {
            int k = r & 63;
            double a = (k == 0 || k == 63) ? (1.0 / 126.0) : (2.0 / 126.0);
            double th = PI2 * (double)(k * c) / 126.0;
            v2 = (r < 64) ? (float)(a * cos(th)) : (float)(-a * sin(th));
        }
        splitf(v2, BIh[i], BIl[i]);
        {
            int ky = r & 63, h = c & 63;
            double th = PI2 * (double)(ky * h) / 64.0;
            double cs = cos(th), sn = sin(th);
            float g = (float)((r < 64) ? ((c < 64) ? cs : sn) : ((c < 64) ? -sn : cs));
            splitf(g, BGh[i], BGl[i]);
        }
        {
            int h = r & 63, ky = c & 63;
            double th = PI2 * (double)(ky * h) / 64.0;
            double cs = cos(th) / 64.0, sn = sin(th) / 64.0;
            float g = (float)((r < 64) ? ((c < 64) ? cs : -sn) : ((c < 64) ? sn : cs));
            splitf(g, BG2h[i], BG2l[i]);
        }
    }
    if (i < 4096) {
        int ky = i >> 6, kx = i & 63;
        float s1 = 1.f / (1.f + expf(-mwin[i]));
        if (kx == 0 || kx == 63) {
            float s2 = 1.f / (1.f + expf(-mwin[(((64 - ky) & 63) << 6) + kx]));
            s1 = 0.5f * (s1 + s2);
        }
        g_mw[i] = s1;
    }
}

// ---------------- encoder 1x1 conv 3 -> 64 ----------------
__global__ __launch_bounds__(256) void k_enc(const float* __restrict__ xin,
                                             const float* __restrict__ ew,
                                             const float* __restrict__ eb) {
    __shared__ float sx[3 * 126];
    __shared__ float sw[192];
    __shared__ float sb[64];
    int b = blockIdx.x >> 6, h = blockIdx.x & 63;
    int t = threadIdx.x;
    if (t < 192) sw[t] = ew[t];
    if (t < 64)  sb[t] = eb[t];
    for (int idx = t; idx < 378; idx += 256) {
        int j = idx / 126, w = idx % 126;
        sx[idx] = xin[(size_t)(b * 3 + j) * HW_ + h * 126 + w];
    }
    __syncthreads();
    for (int idx = t; idx < 64 * 126; idx += 256) {
        int c = idx / 126, w = idx % 126;
        float v = sb[c] + sw[c * 3] * sx[w] + sw[c * 3 + 1] * sx[126 + w]
                        + sw[c * 3 + 2] * sx[252 + w];
        size_t off = (size_t)(b * 64 + c) * HWP_ + h * 128 + w;
        splitf(v, P0h[off], P0l[off]);
    }
}

// ======================================================================
// mma core: warp tile 32x32, split-bf16 (3 MMAs)
// ======================================================================
#define LDSM4(R0,R1,R2,R3,ADDR)                                              \
    asm volatile("ldmatrix.sync.aligned.m8n8.x4.shared.b16 {%0,%1,%2,%3}, [%4];" \
        : "=r"(R0),"=r"(R1),"=r"(R2),"=r"(R3) : "r"(ADDR))
#define LDSM4T(R0,R1,R2,R3,ADDR)                                             \
    asm volatile("ldmatrix.sync.aligned.m8n8.x4.trans.shared.b16 {%0,%1,%2,%3}, [%4];" \
        : "=r"(R0),"=r"(R1),"=r"(R2),"=r"(R3) : "r"(ADDR))
#define MMA16816(D,A,B)                                                      \
    asm volatile("mma.sync.aligned.m16n8k16.row.col.f32.bf16.bf16.f32 "      \
        "{%0,%1,%2,%3}, {%4,%5,%6,%7}, {%8,%9}, {%0,%1,%2,%3};"              \
        : "+f"((D)[0]),"+f"((D)[1]),"+f"((D)[2]),"+f"((D)[3])                \
        : "r"((A)[0]),"r"((A)[1]),"r"((A)[2]),"r"((A)[3]),                   \
          "r"((B)[0]),"r"((B)[1]))

template<int SA, int SB, int KSTEPS>
__device__ __forceinline__ void mma_core(
    const bf16* Ah, const bf16* Al, const bf16* Bh, const bf16* Bl,
    int m0w, int n0w, int lane, float (&acc)[2][4][4])
{
    unsigned baAh = (unsigned)__cvta_generic_to_shared(Ah);
    unsigned baAl = (unsigned)__cvta_generic_to_shared(Al);
    unsigned baBh = (unsigned)__cvta_generic_to_shared(Bh);
    unsigned baBl = (unsigned)__cvta_generic_to_shared(Bl);
    int aRow = m0w + (lane & 15);
    int aCol = (lane >> 4) << 3;
    int bRow = lane & 15;
    int bCol = n0w + ((lane >> 4) << 3);
#pragma unroll
    for (int ks = 0; ks < KSTEPS; ks++) {
        uint32_t ah[2][4], al[2][4], bh[4][2], bl[4][2];
#pragma unroll
        for (int mt = 0; mt < 2; mt++) {
            unsigned offA = (unsigned)((aRow + mt * 16) * SA + ks * 16 + aCol) * 2u;
            LDSM4(ah[mt][0], ah[mt][1], ah[mt][2], ah[mt][3], baAh + offA);
            LDSM4(al[mt][0], al[mt][1], al[mt][2], al[mt][3], baAl + offA);
        }
#pragma unroll
        for (int np = 0; np < 2; np++) {
            unsigned offB = (unsigned)((ks * 16 + bRow) * SB + bCol + np * 16) * 2u;
            LDSM4T(bh[2*np][0], bh[2*np][1], bh[2*np+1][0], bh[2*np+1][1], baBh + offB);
            LDSM4T(bl[2*np][0], bl[2*np][1], bl[2*np+1][0], bl[2*np+1][1], baBl + offB);
        }
#pragma unroll
        for (int mt = 0; mt < 2; mt++)
#pragma unroll
            for (int nt = 0; nt < 4; nt++) {
                MMA16816(acc[mt][nt], ah[mt], bh[nt]);
                MMA16816(acc[mt][nt], ah[mt], bl[nt]);
                MMA16816(acc[mt][nt], al[mt], bh[nt]);
            }
    }
}

#define SMEM_MAT (128 * 136)
#define RACC _Pragma("unroll") for (int a_ = 0; a_ < 2; a_++)                \
    _Pragma("unroll") for (int b_ = 0; b_ < 4; b_++)                         \
    _Pragma("unroll") for (int c_ = 0; c_ < 4; c_++) acc[a_][b_][c_] = 0.f;

// ======================================================================
// FUSED forward: widthDFT -> (smem transpose) -> heightDFT*mw -> g_p1
// CTA = 2 bc. MMA1: C1[(bc,h)][(ri,kx)] = P0 * BW. Transpose to
// B2[(ri,h)][(bc,kx)], MMA2: C2[(ri,ky)][(bc,kx)] = BG * B2.
// ======================================================================
__global__ __launch_bounds__(512) void k_fwd_fused() {
    extern __shared__ __align__(16) char smraw[];
    bf16* Ah = (bf16*)smraw;
    bf16* Al = Ah + SMEM_MAT;
    bf16* Bh = Al + SMEM_MAT;
    bf16* Bl = Bh + SMEM_MAT;
    int t = threadIdx.x, lane = t & 31, warp = t >> 5;
    int m0w = (warp >> 2) * 32, n0w = (warp & 3) * 32;
    int rb = m0w + (lane >> 2), cb = n0w + (lane & 3) * 2;
    int bcBase = blockIdx.x * 2;

    // phase 1 staging: A = P0 (2 bc), B = BW
    const uint4* sAh = (const uint4*)(P0h + (size_t)blockIdx.x * 16384);
    const uint4* sAl = (const uint4*)(P0l + (size_t)blockIdx.x * 16384);
    const uint4* sBh = (const uint4*)BWh;
    const uint4* sBl = (const uint4*)BWl;
    for (int idx = t; idx < 2048; idx += 512) {
        int r = idx >> 4, c = idx & 15;
        *(uint4*)(Ah + r * 136 + c * 8) = sAh[idx];
        *(uint4*)(Al + r * 136 + c * 8) = sAl[idx];
        *(uint4*)(Bh + r * 136 + c * 8) = sBh[idx];
        *(uint4*)(Bl + r * 136 + c * 8) = sBl[idx];
    }
    __syncthreads();
    float acc[2][4][4];
    RACC
    mma_core<136, 136, 8>(Ah, Al, Bh, Bl, m0w, n0w, lane, acc);
    __syncthreads();

    // restage: A <- BG planes ; B <- transpose(C1) split
    const uint4* gAh = (const uint4*)BGh;
    const uint4* gAl = (const uint4*)BGl;
    for (int idx = t; idx < 2048; idx += 512) {
        int r = idx >> 4, c = idx & 15;
        *(uint4*)(Ah + r * 136 + c * 8) = gAh[idx];
        *(uint4*)(Al + r * 136 + c * 8) = gAl[idx];
    }
#pragma unroll
    for (int mt = 0; mt < 2; mt++)
#pragma unroll
        for (int nt = 0; nt < 4; nt++) {
            int col = cb + nt * 8;
            int jc = (col >> 6) * 64, c2b = col & 63;
            int r0 = rb + mt * 16, r1 = r0 + 8;
            int j0 = jc + (r0 & 63), c20 = (r0 >> 6) * 64 + c2b;
            int j1 = jc + (r1 & 63), c21 = (r1 >> 6) * 64 + c2b;
            split_store2(Bh, Bl, (size_t)j0 * 136 + c20, acc[mt][nt][0], acc[mt][nt][1]);
            split_store2(Bh, Bl, (size_t)j1 * 136 + c21, acc[mt][nt][2], acc[mt][nt][3]);
        }
    __syncthreads();
    RACC
    mma_core<136, 136, 8>(Ah, Al, Bh, Bl, m0w, n0w, lane, acc);

    // epilogue: rows m=(ri,ky), cols (bc,kx); *mw; pack to g_p1
    int rb2 = rb, cb2 = cb;
#pragma unroll
    for (int mt = 0; mt < 2; mt++)
#pragma unroll
        for (int nt = 0; nt < 4; nt++) {
            int col = cb2 + nt * 8;
            int bc = bcBase + (col >> 6), kx = col & 63;
            int r0 = rb2 + mt * 16, r1 = r0 + 8;
            float2 w0 = *(const float2*)(g_mw + (r0 & 63) * 64 + kx);
            float2 w1 = *(const float2*)(g_mw + (r1 & 63) * 64 + kx);
            *(uint2*)(g_p1 + (size_t)bc * 8192 + r0 * 64 + kx) =
                make_uint2(pack_split(acc[mt][nt][0] * w0.x), pack_split(acc[mt][nt][1] * w0.y));
            *(uint2*)(g_p1 + (size_t)bc * 8192 + r1 * 64 + kx) =
                make_uint2(pack_split(acc[mt][nt][2] * w1.x), pack_split(acc[mt][nt][3] * w1.y));
        }
}

// ======================================================================
// FUSED inverse: heightIDFT -> (smem transpose) -> widthIDFT+bias+GELU -> P0
// CTA = 2 bc. MMA1: C2[(ri2,h)][(bc,kx)] = BG2 * B1(g_p1). Transpose to
// A2[(bc,h)][(ri2,kx)], MMA2: C3[(bc,h)][w] = A2 * BI.
// ======================================================================
__global__ __launch_bounds__(512) void k_inv_fused(const float* __restrict__ sb,
                                                   const float* __restrict__ mb_) {
    extern __shared__ __align__(16) char smraw[];
    bf16* Ah = (bf16*)smraw;
    bf16* Al = Ah + SMEM_MAT;
    bf16* Bh = Al + SMEM_MAT;
    bf16* Bl = Bh + SMEM_MAT;
    int t = threadIdx.x, lane = t & 31, warp = t >> 5;
    int m0w = (warp >> 2) * 32, n0w = (warp & 3) * 32;
    int rb = m0w + (lane >> 2), cb = n0w + (lane & 3) * 2;
    int bcBase = blockIdx.x * 2;

    // phase 1 staging: A = BG2 planes; B = unpack g_p1
    const uint4* gAh = (const uint4*)BG2h;
    const uint4* gAl = (const uint4*)BG2l;
    for (int idx = t; idx < 2048; idx += 512) {
        int r = idx >> 4, c = idx & 15;
        *(uint4*)(Ah + r * 136 + c * 8) = gAh[idx];
        *(uint4*)(Al + r * 136 + c * 8) = gAl[idx];
    }
    for (int idx = t; idx < 8192; idx += 512) {
        int r = idx >> 6, pc = idx & 63;
        int col0 = pc * 2;
        uint2 p = *(const uint2*)(g_p1 + (size_t)(bcBase + (col0 >> 6)) * 8192
                                  + r * 64 + (col0 & 63));
        *(u32*)(Bh + r * 136 + col0) = prmtf(p.x, p.y, 0x5410);
        *(u32*)(Bl + r * 136 + col0) = prmtf(p.x, p.y, 0x7632);
    }
    __syncthreads();
    float acc[2][4][4];
    RACC
    mma_core<136, 136, 8>(Ah, Al, Bh, Bl, m0w, n0w, lane, acc);
    __syncthreads();

    // restage: A <- transpose(C2) split ; B <- BI planes
    const uint4* sBh = (const uint4*)BIh;
    const uint4* sBl = (const uint4*)BIl;
    for (int idx = t; idx < 2048; idx += 512) {
        int r = idx >> 4, c = idx & 15;
        *(uint4*)(Bh + r * 136 + c * 8) = sBh[idx];
        *(uint4*)(Bl + r * 136 + c * 8) = sBl[idx];
    }
#pragma unroll
    for (int mt = 0; mt < 2; mt++)
#pragma unroll
        for (int nt = 0; nt < 4; nt++) {
            int col = cb + nt * 8;
            int rowc = (col >> 6) * 64, c2b = col & 63;
            int r0 = rb + mt * 16, r1 = r0 + 8;
            int a0 = rowc + (r0 & 63), c20 = (r0 >> 6) * 64 + c2b;
            int a1 = rowc + (r1 & 63), c21 = (r1 >> 6) * 64 + c2b;
            split_store2(Ah, Al, (size_t)a0 * 136 + c20, acc[mt][nt][0], acc[mt][nt][1]);
            split_store2(Ah, Al, (size_t)a1 * 136 + c21, acc[mt][nt][2], acc[mt][nt][3]);
        }
    __syncthreads();
    RACC
    mma_core<136, 136, 8>(Ah, Al, Bh, Bl, m0w, n0w, lane, acc);

    // epilogue: rows (bc,h), cols w; bias + exact GELU -> P0 planes
#pragma unroll
    for (int mt = 0; mt < 2; mt++)
#pragma unroll
        for (int nt = 0; nt < 4; nt++) {
            int col = cb + nt * 8;
            if (col >= 126) continue;
            int r0 = rb + mt * 16, r1 = r0 + 8;
            int bc0 = bcBase + (r0 >> 6), h0 = r0 & 63;
            int bc1 = bcBase + (r1 >> 6), h1 = r1 & 63;
            float bias0 = __ldg(sb + (bc0 & 63)) + __ldg(mb_ + (bc0 & 63));
            float bias1 = __ldg(sb + (bc1 & 63)) + __ldg(mb_ + (bc1 & 63));
            split_store2(P0h, P0l, (size_t)bc0 * HWP_ + h0 * 128 + col,
                         gelu_f(acc[mt][nt][0] + bias0), gelu_f(acc[mt][nt][1] + bias0));
            split_store2(P0h, P0l, (size_t)bc1 * HWP_ + h1 * 128 + col,
                         gelu_f(acc[mt][nt][2] + bias1), gelu_f(acc[mt][nt][3] + bias1));
        }
}

// ---------------- transpose to mode-major (packed u32) ----------------
__global__ __launch_bounds__(256) void k_t1() {
    __shared__ u32 s[128 * 65];
    int b = blockIdx.x >> 6, ky = blockIdx.x & 63;
    int t = threadIdx.x;
    for (int idx = t; idx < 8192; idx += 256) {
        int i = idx >> 7, r = idx & 127, ri = r >> 6, kx = r & 63;
        s[(ri * 64 + i) * 65 + kx] =
            g_p1[(size_t)(b * 64 + i) * 8192 + ri * 4096 + ky * 64 + kx];
    }
    __syncthreads();
    for (int idx = t; idx < 8192; idx += 256) {
        int kx = idx >> 7, c = idx & 127;
        g_p2[(size_t)(ky * 64 + kx) * 16384 + b * 128 + c] = s[c * 65 + kx];
    }
}

// ---------------- transpose back from mode-major (packed u32) ----------------
__global__ __launch_bounds__(256) void k_t2() {
    __shared__ u32 s[128 * 65];
    int b = blockIdx.x >> 6, ky = blockIdx.x & 63;
    int t = threadIdx.x;
    for (int idx = t; idx < 8192; idx += 256) {
        int kx = idx >> 7, c = idx & 127;
        s[c * 65 + kx] = g_p3[(size_t)(ky * 64 + kx) * 16384 + b * 128 + c];
    }
    __syncthreads();
    for (int idx = t; idx < 8192; idx += 256) {
        int o = idx >> 7, r = idx & 127, ri = r >> 6, kx = r & 63;
        g_p1[(size_t)(b * 64 + o) * 8192 + ri * 4096 + ky * 64 + kx] =
            s[(ri * 64 + o) * 65 + kx];
    }
}

// ---------------- weight fold (writes split planes) ----------------
__global__ void k_wt(const float* __restrict__ spec, const float* __restrict__ mlp) {
    __shared__ float tile[32][33];
    int x = blockIdx.x * 32 + threadIdx.x;   // mode
    int yb = blockIdx.y * 32;                // io
#pragma unroll
    for (int j = 0; j < 32; j += 8)
        tile[threadIdx.y + j][threadIdx.x] = spec[(size_t)(yb + threadIdx.y + j) * 4096 + x];
    __syncthreads();
    int io2 = yb + threadIdx.x;
    float madd = mlp[(io2 & 63) * 64 + (io2 >> 6)];
    int mb = blockIdx.x * 32;
#pragma unroll
    for (int j = 0; j < 32; j += 8) {
        float v = tile[threadIdx.x][threadIdx.y + j] + madd;
        size_t off = (size_t)(mb + threadIdx.y + j) * 4096 + io2;
        splitf(v, WTh[off], WTl[off]);
    }
}

// ======================================================================
// per-mode GEMM: C[256 x 64] = X[256 x 64] W[64 x 64], K=64
// ======================================================================
__global__ __launch_bounds__(512) void k_sgemm() {
    extern __shared__ __align__(16) char smraw[];
    bf16* Ah = (bf16*)smraw;            // [256][72]
    bf16* Al = Ah + 256 * 72;
    bf16* Bh = Al + 256 * 72;           // [64][72]
    bf16* Bl = Bh + 64 * 72;
    int t = threadIdx.x, lane = t & 31, warp = t >> 5;
    int mode = blockIdx.x;
    const u32* asrc = g_p2 + (size_t)mode * 16384;
    for (int idx = t; idx < 8192; idx += 512) {
        int r = idx >> 5, pc = idx & 31;
        int col0 = pc * 2;
        uint2 p = *(const uint2*)(asrc + r * 64 + col0);
        *(u32*)(Ah + r * 72 + col0) = prmtf(p.x, p.y, 0x5410);
        *(u32*)(Al + r * 72 + col0) = prmtf(p.x, p.y, 0x7632);
    }
    const uint4* sBh = (const uint4*)(WTh + (size_t)mode * 4096);
    const uint4* sBl = (const uint4*)(WTl + (size_t)mode * 4096);
    for (int idx = t; idx < 512; idx += 512) {
        int r = idx >> 3, c = idx & 7;
        *(uint4*)(Bh + r * 72 + c * 8) = sBh[idx];
        *(uint4*)(Bl + r * 72 + c * 8) = sBl[idx];
    }
    __syncthreads();
    int m0w = (warp >> 1) * 32, n0w = (warp & 1) * 32;
    float acc[2][4][4];
    RACC
    mma_core<72, 72, 4>(Ah, Al, Bh, Bl, m0w, n0w, lane, acc);
    int rb = m0w + (lane >> 2), cb = n0w + (lane & 3) * 2;
    u32* dst = g_p3 + (size_t)mode * 16384;
#pragma unroll
    for (int mt = 0; mt < 2; mt++)
#pragma unroll
        for (int nt = 0; nt < 4; nt++) {
            int col = cb + nt * 8;
            int r0 = rb + mt * 16, r1 = r0 + 8;
            *(uint2*)(dst + r0 * 64 + col) =
                make_uint2(pack_split(acc[mt][nt][0]), pack_split(acc[mt][nt][1]));
            *(uint2*)(dst + r1 * 64 + col) =
                make_uint2(pack_split(acc[mt][nt][2]), pack_split(acc[mt][nt][3]));
        }
}

// ---------------- decoder 1x1 conv 64 -> 1 ----------------
__global__ __launch_bounds__(256) void k_dec(const float* __restrict__ dw,
                                             const float* __restrict__ db,
                                             float* __restrict__ out) {
    __shared__ float sw[64];
    int b = blockIdx.x, t = threadIdx.x;
    if (t < 64) sw[t] = dw[t];
    __syncthreads();
    float bias = __ldg(db);
    for (int p = t; p < HWP_; p += 256) {
        int w = p & 127;
        if (w >= 126) continue;
        int h = p >> 7;
        float s = bias;
        size_t base = (size_t)b * 64 * HWP_ + p;
#pragma unroll 8
        for (int c = 0; c < 64; c++) {
            size_t off = base + (size_t)c * HWP_;
            s = fmaf(sw[c], __bfloat162float(P0h[off]) + __bfloat162float(P0l[off]), s);
        }
        out[(size_t)b * HW_ + h * 126 + w] = s;
    }
}

extern "C" void kernel_launch(void* const* d_in, const int* in_sizes, int n_in,
                              void* d_out, int out_size) {
    const float* x       = (const float*)d_in[0];
    const float* mode_w  = (const float*)d_in[1];
    const float* enc_w   = (const float*)d_in[2];
    const float* enc_b   = (const float*)d_in[3];
    const float* dec_w   = (const float*)d_in[4];
    const float* dec_b   = (const float*)d_in[5];
    const float* spec_w  = (const float*)d_in[6];
    const float* spec_b  = (const float*)d_in[7];
    const float* mlp_w   = (const float*)d_in[8];
    const float* mlp_b   = (const float*)d_in[9];
    float* out = (float*)d_out;

    const int smemBig = 4 * SMEM_MAT * 2;                     // 139,264 B
    const int smemS   = (2 * 256 * 72 + 2 * 64 * 72) * 2;     //  92,160 B
    cudaFuncSetAttribute(k_fwd_fused, cudaFuncAttributeMaxDynamicSharedMemorySize, smemBig);
    cudaFuncSetAttribute(k_inv_fused, cudaFuncAttributeMaxDynamicSharedMemorySize, smemBig);
    cudaFuncSetAttribute(k_sgemm,     cudaFuncAttributeMaxDynamicSharedMemorySize, smemS);

    k_basis<<<64, 256>>>(mode_w);
    k_enc<<<8192, 256>>>(x, enc_w, enc_b);

    for (int l = 0; l < 4; l++) {
        k_wt<<<dim3(128, 128), dim3(32, 8)>>>(spec_w + (size_t)l * 16777216,
                                              mlp_w + (size_t)l * 4096);
        k_fwd_fused<<<4096, 512, smemBig>>>();
        k_t1<<<8192, 256>>>();
        k_sgemm<<<4096, 512, smemS>>>();
        k_t2<<<8192, 256>>>();
        k_inv_fused<<<4096, 512, smemBig>>>(spec_b + l * 64, mlp_b + l * 64);
    }
    k_dec<<<128, 256>>>(dec_w, dec_b, out);
}

// round 16
// speedup vs baseline: 1.0349x; 1.0187x over previous
#include <cuda_runtime.h>
#include <cuda_bf16.h>
#include <math.h>
#include <stdint.h>

#define HW_   8064          // 64*126
#define HWP_  8192          // padded spatial: 64*128
#define BC_   8192          // 128*64
#define NMODE 4096          // 64*64

typedef __nv_bfloat16 bf16;
typedef unsigned int u32;

// ---------------- device scratch ----------------
__device__ __align__(16) bf16 P0h[BC_ * (size_t)HWP_];
__device__ __align__(16) bf16 P0l[BC_ * (size_t)HWP_];
__device__ __align__(16) u32  g_p1[BC_ * (size_t)8192];      // bc-major packed
__device__ __align__(16) u32  g_p2[NMODE * (size_t)16384];   // mode-major packed
__device__ __align__(16) u32  g_p3[NMODE * (size_t)16384];   // mode-major packed
__device__ __align__(16) bf16 WTh[NMODE * (size_t)4096];
__device__ __align__(16) bf16 WTl[NMODE * (size_t)4096];
__device__ __align__(16) bf16 BWh[16384],  BWl[16384];    // fwd width  [w][n]
__device__ __align__(16) bf16 BIh[16384],  BIl[16384];    // inv width  [n][w]
__device__ __align__(16) bf16 BGh[16384],  BGl[16384];    // fwd height [m][j]
__device__ __align__(16) bf16 BG2h[16384], BG2l[16384];   // inv height [m][j]
__device__ float g_mw[4096];

// ---------------- helpers ----------------
__device__ __forceinline__ void splitf(float v, bf16& h, bf16& l) {
    h = __float2bfloat16(v);
    l = __float2bfloat16(v - __bfloat162float(h));
}
__device__ __forceinline__ u32 pack_split(float v) {
    bf16 h, l; splitf(v, h, l);
    return (u32)__bfloat16_as_ushort(h) | ((u32)__bfloat16_as_ushort(l) << 16);
}
__device__ __forceinline__ void split_store2(bf16* H, bf16* L, size_t off, float a, float b) {
    bf16 ha, la, hb, lb; splitf(a, ha, la); splitf(b, hb, lb);
    *(__nv_bfloat162*)(H + off) = __halves2bfloat162(ha, hb);
    *(__nv_bfloat162*)(L + off) = __halves2bfloat162(la, lb);
}
__device__ __forceinline__ u32 prmtf(u32 a, u32 b, u32 s) {
    u32 d; asm("prmt.b32 %0,%1,%2,%3;" : "=r"(d) : "r"(a), "r"(b), "r"(s)); return d;
}
__device__ __forceinline__ float gelu_f(float v) {
    return 0.5f * v * (1.0f + erff(v * 0.70710678118654752f));
}

// ---------------- basis precompute (split planes) ----------------
__global__ void k_basis(const float* __restrict__ mwin) {
    int i = blockIdx.x * blockDim.x + threadIdx.x;
    const double PI2 = 6.283185307179586476925286766559;
    if (i < 16384) {
        int r = i >> 7, c = i & 127;
        float v = 0.f;
        if (r < 126) {
            int k = c & 63;
            double th = PI2 * (double)(k * r) / 126.0;
            v = (c < 64) ? (float)cos(th) : (float)(-sin(th));
        }
        splitf(v, BWh[i], BWl[i]);
        float v2 = 0.f;
        if (c < 126) {
            int k = r & 63;
            double a = (k == 0 || k == 63) ? (1.0 / 126.0) : (2.0 / 126.0);
            double th = PI2 * (double)(k * c) / 126.0;
            v2 = (r < 64) ? (float)(a * cos(th)) : (float)(-a * sin(th));
        }
        splitf(v2, BIh[i], BIl[i]);
        {
            int ky = r & 63, h = c & 63;
            double th = PI2 * (double)(ky * h) / 64.0;
            double cs = cos(th), sn = sin(th);
            float g = (float)((r < 64) ? ((c < 64) ? cs : sn) : ((c < 64) ? -sn : cs));
            splitf(g, BGh[i], BGl[i]);
        }
        {
            int h = r & 63, ky = c & 63;
            double th = PI2 * (double)(ky * h) / 64.0;
            double cs = cos(th) / 64.0, sn = sin(th) / 64.0;
            float g = (float)((r < 64) ? ((c < 64) ? cs : -sn) : ((c < 64) ? sn : cs));
            splitf(g, BG2h[i], BG2l[i]);
        }
    }
    if (i < 4096) {
        int ky = i >> 6, kx = i & 63;
        float s1 = 1.f / (1.f + expf(-mwin[i]));
        if (kx == 0 || kx == 63) {
            float s2 = 1.f / (1.f + expf(-mwin[(((64 - ky) & 63) << 6) + kx]));
            s1 = 0.5f * (s1 + s2);
        }
        g_mw[i] = s1;
    }
}

// ---------------- encoder 1x1 conv 3 -> 64 ----------------
__global__ __launch_bounds__(256) void k_enc(const float* __restrict__ xin,
                                             const float* __restrict__ ew,
                                             const float* __restrict__ eb) {
    __shared__ float sx[3 * 126];
    __shared__ float sw[192];
    __shared__ float sb[64];
    int b = blockIdx.x >> 6, h = blockIdx.x & 63;
    int t = threadIdx.x;
    if (t < 192) sw[t] = ew[t];
    if (t < 64)  sb[t] = eb[t];
    for (int idx = t; idx < 378; idx += 256) {
        int j = idx / 126, w = idx % 126;
        sx[idx] = xin[(size_t)(b * 3 + j) * HW_ + h * 126 + w];
    }
    __syncthreads();
    for (int idx = t; idx < 64 * 126; idx += 256) {
        int c = idx / 126, w = idx % 126;
        float v = sb[c] + sw[c * 3] * sx[w] + sw[c * 3 + 1] * sx[126 + w]
                        + sw[c * 3 + 2] * sx[252 + w];
        size_t off = (size_t)(b * 64 + c) * HWP_ + h * 128 + w;
        splitf(v, P0h[off], P0l[off]);
    }
}

// ======================================================================
// mma core: warp tile 32x32, split-bf16 (3 MMAs)
// ======================================================================
#define LDSM4(R0,R1,R2,R3,ADDR)                                              \
    asm volatile("ldmatrix.sync.aligned.m8n8.x4.shared.b16 {%0,%1,%2,%3}, [%4];" \
        : "=r"(R0),"=r"(R1),"=r"(R2),"=r"(R3) : "r"(ADDR))
#define LDSM4T(R0,R1,R2,R3,ADDR)                                             \
    asm volatile("ldmatrix.sync.aligned.m8n8.x4.trans.shared.b16 {%0,%1,%2,%3}, [%4];" \
        : "=r"(R0),"=r"(R1),"=r"(R2),"=r"(R3) : "r"(ADDR))
#define MMA16816(D,A,B)                                                      \
    asm volatile("mma.sync.aligned.m16n8k16.row.col.f32.bf16.bf16.f32 "      \
        "{%0,%1,%2,%3}, {%4,%5,%6,%7}, {%8,%9}, {%0,%1,%2,%3};"              \
        : "+f"((D)[0]),"+f"((D)[1]),"+f"((D)[2]),"+f"((D)[3])                \
        : "r"((A)[0]),"r"((A)[1]),"r"((A)[2]),"r"((A)[3]),                   \
          "r"((B)[0]),"r"((B)[1]))

template<int SA, int SB, int KSTEPS>
__device__ __forceinline__ void mma_core(
    const bf16* Ah, const bf16* Al, const bf16* Bh, const bf16* Bl,
    int m0w, int n0w, int lane, float (&acc)[2][4][4])
{
    unsigned baAh = (unsigned)__cvta_generic_to_shared(Ah);
    unsigned baAl = (unsigned)__cvta_generic_to_shared(Al);
    unsigned baBh = (unsigned)__cvta_generic_to_shared(Bh);
    unsigned baBl = (unsigned)__cvta_generic_to_shared(Bl);
    int aRow = m0w + (lane & 15);
    int aCol = (lane >> 4) << 3;
    int bRow = lane & 15;
    int bCol = n0w + ((lane >> 4) << 3);
#pragma unroll
    for (int ks = 0; ks < KSTEPS; ks++) {
        uint32_t ah[2][4], al[2][4], bh[4][2], bl[4][2];
#pragma unroll
        for (int mt = 0; mt < 2; mt++) {
            unsigned offA = (unsigned)((aRow + mt * 16) * SA + ks * 16 + aCol) * 2u;
            LDSM4(ah[mt][0], ah[mt][1], ah[mt][2], ah[mt][3], baAh + offA);
            LDSM4(al[mt][0], al[mt][1], al[mt][2], al[mt][3], baAl + offA);
        }
#pragma unroll
        for (int np = 0; np < 2; np++) {
            unsigned offB = (unsigned)((ks * 16 + bRow) * SB + bCol + np * 16) * 2u;
            LDSM4T(bh[2*np][0], bh[2*np][1], bh[2*np+1][0], bh[2*np+1][1], baBh + offB);
            LDSM4T(bl[2*np][0], bl[2*np][1], bl[2*np+1][0], bl[2*np+1][1], baBl + offB);
        }
#pragma unroll
        for (int mt = 0; mt < 2; mt++)
#pragma unroll
            for (int nt = 0; nt < 4; nt++) {
                MMA16816(acc[mt][nt], ah[mt], bh[nt]);
                MMA16816(acc[mt][nt], ah[mt], bl[nt]);
                MMA16816(acc[mt][nt], al[mt], bh[nt]);
            }
    }
}

#define XPLANE 9216            // max(64*136, 128*72)
#define YPLANE (128 * 136)
#define RACC _Pragma("unroll") for (int a_ = 0; a_ < 2; a_++)                \
    _Pragma("unroll") for (int b_ = 0; b_ < 4; b_++)                         \
    _Pragma("unroll") for (int c_ = 0; c_ < 4; c_++) acc[a_][b_][c_] = 0.f;

// ======================================================================
// FUSED forward, 1 bc per CTA, 256 thr (8 warps):
// phase1: C1[h 64][n 128] = act[64][128] * BW[128][128]   (X=act, Y=BW)
// transpose C1 -> X as B2[(ri*64+h) 128][kx 64] (stride 72)
// phase2: C2[(ri,ky) 128][kx 64] = BG[128][128] * B2      (Y=BG)
// epilogue: *mw -> g_p1[bc]
// ======================================================================
__global__ __launch_bounds__(256) void k_fwd_fused() {
    extern __shared__ __align__(16) char smraw[];
    bf16* Xh = (bf16*)smraw;
    bf16* Xl = Xh + XPLANE;
    bf16* Yh = Xl + XPLANE;
    bf16* Yl = Yh + YPLANE;
    int t = threadIdx.x, lane = t & 31, warp = t >> 5;
    int bc = blockIdx.x;

    // stage X <- act [64 rows][128 cols] (stride 136), Y <- BW [128][136]
    const uint4* aH = (const uint4*)(P0h + (size_t)bc * HWP_);
    const uint4* aL = (const uint4*)(P0l + (size_t)bc * HWP_);
    for (int idx = t; idx < 1024; idx += 256) {
        int r = idx >> 4, c = idx & 15;
        *(uint4*)(Xh + r * 136 + c * 8) = aH[idx];
        *(uint4*)(Xl + r * 136 + c * 8) = aL[idx];
    }
    const uint4* bH = (const uint4*)BWh;
    const uint4* bL = (const uint4*)BWl;
    for (int idx = t; idx < 2048; idx += 256) {
        int r = idx >> 4, c = idx & 15;
        *(uint4*)(Yh + r * 136 + c * 8) = bH[idx];
        *(uint4*)(Yl + r * 136 + c * 8) = bL[idx];
    }
    __syncthreads();

    // phase 1: 8 warps over 64x128
    int m0w1 = (warp >> 2) * 32, n0w1 = (warp & 3) * 32;
    float acc[2][4][4];
    RACC
    mma_core<136, 136, 8>(Xh, Xl, Yh, Yl, m0w1, n0w1, lane, acc);
    __syncthreads();

    // restage Y <- BG; transpose C1 into X as B2 [128][72]
    const uint4* gH = (const uint4*)BGh;
    const uint4* gL = (const uint4*)BGl;
    for (int idx = t; idx < 2048; idx += 256) {
        int r = idx >> 4, c = idx & 15;
        *(uint4*)(Yh + r * 136 + c * 8) = gH[idx];
        *(uint4*)(Yl + r * 136 + c * 8) = gL[idx];
    }
    {
        int rb = m0w1 + (lane >> 2), cb = n0w1 + (lane & 3) * 2;
#pragma unroll
        for (int mt = 0; mt < 2; mt++)
#pragma unroll
            for (int nt = 0; nt < 4; nt++) {
                int col = cb + nt * 8;
                int base = (col >> 6) * 64, c2 = col & 63;
                int r0 = rb + mt * 16, r1 = r0 + 8;
                split_store2(Xh, Xl, (size_t)(base + r0) * 72 + c2,
                             acc[mt][nt][0], acc[mt][nt][1]);
                split_store2(Xh, Xl, (size_t)(base + r1) * 72 + c2,
                             acc[mt][nt][2], acc[mt][nt][3]);
            }
    }
    __syncthreads();

    // phase 2: 8 warps over 128x64
    int m0w2 = (warp >> 1) * 32, n0w2 = (warp & 1) * 32;
    RACC
    mma_core<136, 72, 8>(Yh, Yl, Xh, Xl, m0w2, n0w2, lane, acc);

    // epilogue: rows m=(ri,ky), cols kx; *mw; pack -> g_p1[bc]
    int rb2 = m0w2 + (lane >> 2), cb2 = n0w2 + (lane & 3) * 2;
#pragma unroll
    for (int mt = 0; mt < 2; mt++)
#pragma unroll
        for (int nt = 0; nt < 4; nt++) {
            int kx = cb2 + nt * 8;
            int m0 = rb2 + mt * 16, m1 = m0 + 8;
            float2 w0 = *(const float2*)(g_mw + (m0 & 63) * 64 + kx);
            float2 w1 = *(const float2*)(g_mw + (m1 & 63) * 64 + kx);
            *(uint2*)(g_p1 + (size_t)bc * 8192 + m0 * 64 + kx) =
                make_uint2(pack_split(acc[mt][nt][0] * w0.x), pack_split(acc[mt][nt][1] * w0.y));
            *(uint2*)(g_p1 + (size_t)bc * 8192 + m1 * 64 + kx) =
                make_uint2(pack_split(acc[mt][nt][2] * w1.x), pack_split(acc[mt][nt][3] * w1.y));
        }
}

// ======================================================================
// FUSED inverse, 1 bc per CTA, 256 thr:
// phase1: C2'[(ri2,h) 128][kx 64] = BG2[128][128] * B1[(ri,ky) 128][kx 64]
// transpose C2' -> X as A2[h 64][(ri2,kx) 128] (stride 136)
// phase2: C3[h 64][w 128] = A2 * BI[128][128]; bias+GELU -> P0[bc]
// ======================================================================
__global__ __launch_bounds__(256) void k_inv_fused(const float* __restrict__ sb,
                                                   const float* __restrict__ mb_) {
    extern __shared__ __align__(16) char smraw[];
    bf16* Xh = (bf16*)smraw;
    bf16* Xl = Xh + XPLANE;
    bf16* Yh = Xl + XPLANE;
    bf16* Yl = Yh + YPLANE;
    int t = threadIdx.x, lane = t & 31, warp = t >> 5;
    int bc = blockIdx.x;

    // stage Y <- BG2; X <- unpack g_p1[bc] as [128][72]
    const uint4* gH = (const uint4*)BG2h;
    const uint4* gL = (const uint4*)BG2l;
    for (int idx = t; idx < 2048; idx += 256) {
        int r = idx >> 4, c = idx & 15;
        *(uint4*)(Yh + r * 136 + c * 8) = gH[idx];
        *(uint4*)(Yl + r * 136 + c * 8) = gL[idx];
    }
    const u32* src = g_p1 + (size_t)bc * 8192;
    for (int idx = t; idx < 4096; idx += 256) {
        int r = idx >> 5, pc = idx & 31;
        int col0 = pc * 2;
        uint2 p = *(const uint2*)(src + r * 64 + col0);
        *(u32*)(Xh + r * 72 + col0) = prmtf(p.x, p.y, 0x5410);
        *(u32*)(Xl + r * 72 + col0) = prmtf(p.x, p.y, 0x7632);
    }
    __syncthreads();

    // phase 1: 128x64
    int m0w1 = (warp >> 1) * 32, n0w1 = (warp & 1) * 32;
    float acc[2][4][4];
    RACC
    mma_core<136, 72, 8>(Yh, Yl, Xh, Xl, m0w1, n0w1, lane, acc);
    __syncthreads();

    // restage Y <- BI; transpose C2' into X as A2 [64][136]
    const uint4* iH = (const uint4*)BIh;
    const uint4* iL = (const uint4*)BIl;
    for (int idx = t; idx < 2048; idx += 256) {
        int r = idx >> 4, c = idx & 15;
        *(uint4*)(Yh + r * 136 + c * 8) = iH[idx];
        *(uint4*)(Yl + r * 136 + c * 8) = iL[idx];
    }
    {
        int rb = m0w1 + (lane >> 2), cb = n0w1 + (lane & 3) * 2;
#pragma unroll
        for (int mt = 0; mt < 2; mt++)
#pragma unroll
            for (int nt = 0; nt < 4; nt++) {
                int kx = cb + nt * 8;
                int r0 = rb + mt * 16, r1 = r0 + 8;
                split_store2(Xh, Xl, (size_t)(r0 & 63) * 136 + (r0 >> 6) * 64 + kx,
                             acc[mt][nt][0], acc[mt][nt][1]);
                split_store2(Xh, Xl, (size_t)(r1 & 63) * 136 + (r1 >> 6) * 64 + kx,
                             acc[mt][nt][2], acc[mt][nt][3]);
            }
    }
    __syncthreads();

    // phase 2: 64x128
    int m0w2 = (warp >> 2) * 32, n0w2 = (warp & 3) * 32;
    RACC
    mma_core<136, 136, 8>(Xh, Xl, Yh, Yl, m0w2, n0w2, lane, acc);

    int ch = bc & 63;
    float bias = __ldg(sb + ch) + __ldg(mb_ + ch);
    int rb2 = m0w2 + (lane >> 2), cb2 = n0w2 + (lane & 3) * 2;
#pragma unroll
    for (int mt = 0; mt < 2; mt++)
#pragma unroll
        for (int nt = 0; nt < 4; nt++) {
            int w = cb2 + nt * 8;
            if (w >= 126) continue;
            int h0 = rb2 + mt * 16, h1 = h0 + 8;
            split_store2(P0h, P0l, (size_t)bc * HWP_ + h0 * 128 + w,
                         gelu_f(acc[mt][nt][0] + bias), gelu_f(acc[mt][nt][1] + bias));
            split_store2(P0h, P0l, (size_t)bc * HWP_ + h1 * 128 + w,
                         gelu_f(acc[mt][nt][2] + bias), gelu_f(acc[mt][nt][3] + bias));
        }
}

// ---------------- transpose to mode-major (packed u32) ----------------
__global__ __launch_bounds__(256) void k_t1() {
    __shared__ u32 s[128 * 65];
    int b = blockIdx.x >> 6, ky = blockIdx.x & 63;
    int t = threadIdx.x;
    for (int idx = t; idx < 8192; idx += 256) {
        int i = idx >> 7, r = idx & 127, ri = r >> 6, kx = r & 63;
        s[(ri * 64 + i) * 65 + kx] =
            g_p1[(size_t)(b * 64 + i) * 8192 + ri * 4096 + ky * 64 + kx];
    }
    __syncthreads();
    for (int idx = t; idx < 8192; idx += 256) {
        int kx = idx >> 7, c = idx & 127;
        g_p2[(size_t)(ky * 64 + kx) * 16384 + b * 128 + c] = s[c * 65 + kx];
    }
}

// ---------------- transpose back from mode-major (packed u32) ----------------
__global__ __launch_bounds__(256) void k_t2() {
    __shared__ u32 s[128 * 65];
    int b = blockIdx.x >> 6, ky = blockIdx.x & 63;
    int t = threadIdx.x;
    for (int idx = t; idx < 8192; idx += 256) {
        int kx = idx >> 7, c = idx & 127;
        s[c * 65 + kx] = g_p3[(size_t)(ky * 64 + kx) * 16384 + b * 128 + c];
    }
    __syncthreads();
    for (int idx = t; idx < 8192; idx += 256) {
        int o = idx >> 7, r = idx & 127, ri = r >> 6, kx = r & 63;
        g_p1[(size_t)(b * 64 + o) * 8192 + ri * 4096 + ky * 64 + kx] =
            s[(ri * 64 + o) * 65 + kx];
    }
}

// ---------------- weight fold (writes split planes) ----------------
__global__ void k_wt(const float* __restrict__ spec, const float* __restrict__ mlp) {
    __shared__ float tile[32][33];
    int x = blockIdx.x * 32 + threadIdx.x;   // mode
    int yb = blockIdx.y * 32;                // io
#pragma unroll
    for (int j = 0; j < 32; j += 8)
        tile[threadIdx.y + j][threadIdx.x] = spec[(size_t)(yb + threadIdx.y + j) * 4096 + x];
    __syncthreads();
    int io2 = yb + threadIdx.x;
    float madd = mlp[(io2 & 63) * 64 + (io2 >> 6)];
    int mb = blockIdx.x * 32;
#pragma unroll
    for (int j = 0; j < 32; j += 8) {
        float v = tile[threadIdx.x][threadIdx.y + j] + madd;
        size_t off = (size_t)(mb + threadIdx.y + j) * 4096 + io2;
        splitf(v, WTh[off], WTl[off]);
    }
}

// ======================================================================
// per-mode GEMM: C[256 x 64] = X[256 x 64] W[64 x 64], K=64
// ======================================================================
__global__ __launch_bounds__(512) void k_sgemm() {
    extern __shared__ __align__(16) char smraw[];
    bf16* Ah = (bf16*)smraw;            // [256][72]
    bf16* Al = Ah + 256 * 72;
    bf16* Bh = Al + 256 * 72;           // [64][72]
    bf16* Bl = Bh + 64 * 72;
    int t = threadIdx.x, lane = t & 31, warp = t >> 5;
    int mode = blockIdx.x;
    const u32* asrc = g_p2 + (size_t)mode * 16384;
    for (int idx = t; idx < 8192; idx += 512) {
        int r = idx >> 5, pc = idx & 31;
        int col0 = pc * 2;
        uint2 p = *(const uint2*)(asrc + r * 64 + col0);
        *(u32*)(Ah + r * 72 + col0) = prmtf(p.x, p.y, 0x5410);
        *(u32*)(Al + r * 72 + col0) = prmtf(p.x, p.y, 0x7632);
    }
    const uint4* sBh = (const uint4*)(WTh + (size_t)mode * 4096);
    const uint4* sBl = (const uint4*)(WTl + (size_t)mode * 4096);
    for (int idx = t; idx < 512; idx += 512) {
        int r = idx >> 3, c = idx & 7;
        *(uint4*)(Bh + r * 72 + c * 8) = sBh[idx];
        *(uint4*)(Bl + r * 72 + c * 8) = sBl[idx];
    }
    __syncthreads();
    int m0w = (warp >> 1) * 32, n0w = (warp & 1) * 32;
    float acc[2][4][4];
    RACC
    mma_core<72, 72, 4>(Ah, Al, Bh, Bl, m0w, n0w, lane, acc);
    int rb = m0w + (lane >> 2), cb = n0w + (lane & 3) * 2;
    u32* dst = g_p3 + (size_t)mode * 16384;
#pragma unroll
    for (int mt = 0; mt < 2; mt++)
#pragma unroll
        for (int nt = 0; nt < 4; nt++) {
            int col = cb + nt * 8;
            int r0 = rb + mt * 16, r1 = r0 + 8;
            *(uint2*)(dst + r0 * 64 + col) =
                make_uint2(pack_split(acc[mt][nt][0]), pack_split(acc[mt][nt][1]));
            *(uint2*)(dst + r1 * 64 + col) =
                make_uint2(pack_split(acc[mt][nt][2]), pack_split(acc[mt][nt][3]));
        }
}

// ---------------- decoder 1x1 conv 64 -> 1 ----------------
__global__ __launch_bounds__(256) void k_dec(const float* __restrict__ dw,
                                             const float* __restrict__ db,
                                             float* __restrict__ out) {
    __shared__ float sw[64];
    int b = blockIdx.x, t = threadIdx.x;
    if (t < 64) sw[t] = dw[t];
    __syncthreads();
    float bias = __ldg(db);
    for (int p = t; p < HWP_; p += 256) {
        int w = p & 127;
        if (w >= 126) continue;
        int h = p >> 7;
        float s = bias;
        size_t base = (size_t)b * 64 * HWP_ + p;
#pragma unroll 8
        for (int c = 0; c < 64; c++) {
            size_t off = base + (size_t)c * HWP_;
            s = fmaf(sw[c], __bfloat162float(P0h[off]) + __bfloat162float(P0l[off]), s);
        }
        out[(size_t)b * HW_ + h * 126 + w] = s;
    }
}

extern "C" void kernel_launch(void* const* d_in, const int* in_sizes, int n_in,
                              void* d_out, int out_size) {
    const float* x       = (const float*)d_in[0];
    const float* mode_w  = (const float*)d_in[1];
    const float* enc_w   = (const float*)d_in[2];
    const float* enc_b   = (const float*)d_in[3];
    const float* dec_w   = (const float*)d_in[4];
    const float* dec_b   = (const float*)d_in[5];
    const float* spec_w  = (const float*)d_in[6];
    const float* spec_b  = (const float*)d_in[7];
    const float* mlp_w   = (const float*)d_in[8];
    const float* mlp_b   = (const float*)d_in[9];
    float* out = (float*)d_out;

    const int smemF = (2 * XPLANE + 2 * YPLANE) * 2;          // 106,496 B -> 2 CTA/SM
    const int smemS = (2 * 256 * 72 + 2 * 64 * 72) * 2;       //  92,160 B
    cudaFuncSetAttribute(k_fwd_fused, cudaFuncAttributeMaxDynamicSharedMemorySize, smemF);
    cudaFuncSetAttribute(k_inv_fused, cudaFuncAttributeMaxDynamicSharedMemorySize, smemF);
    cudaFuncSetAttribute(k_sgemm,     cudaFuncAttributeMaxDynamicSharedMemorySize, smemS);

    k_basis<<<64, 256>>>(mode_w);
    k_enc<<<8192, 256>>>(x, enc_w, enc_b);

    for (int l = 0; l < 4; l++) {
        k_wt<<<dim3(128, 128), dim3(32, 8)>>>(spec_w + (size_t)l * 16777216,
                                              mlp_w + (size_t)l * 4096);
        k_fwd_fused<<<8192, 256, smemF>>>();
        k_t1<<<8192, 256>>>();
        k_sgemm<<<4096, 512, smemS>>>();
        k_t2<<<8192, 256>>>();
        k_inv_fused<<<8192, 256, smemF>>>(spec_b + l * 64, mlp_b + l * 64);
    }
    k_dec<<<128, 256>>>(dec_w, dec_b, out);
}

// round 17
// speedup vs baseline: 1.1084x; 1.0711x over previous
#include <cuda_runtime.h>
#include <cuda_bf16.h>
#include <math.h>
#include <stdint.h>

#define HW_   8064          // 64*126
#define HWP_  8192          // padded spatial: 64*128
#define BC_   8192          // 128*64
#define NMODE 4096          // 64*64

typedef __nv_bfloat16 bf16;
typedef unsigned int u32;

// ---------------- device scratch ----------------
__device__ __align__(16) bf16 P0h[BC_ * (size_t)HWP_];
__device__ __align__(16) bf16 P0l[BC_ * (size_t)HWP_];
__device__ __align__(16) u32  g_p1[BC_ * (size_t)8192];      // bc-major packed
__device__ __align__(16) u32  g_p2[NMODE * (size_t)16384];   // mode-major packed
__device__ __align__(16) u32  g_p3[NMODE * (size_t)16384];   // mode-major packed
__device__ __align__(16) bf16 WTh[NMODE * (size_t)4096];
__device__ __align__(16) bf16 WTl[NMODE * (size_t)4096];
__device__ __align__(16) bf16 BWh[16384],  BWl[16384];    // fwd width  [w][n]
__device__ __align__(16) bf16 BIh[16384],  BIl[16384];    // inv width  [n][w]
__device__ __align__(16) bf16 BGh[16384],  BGl[16384];    // fwd height [m][j]
__device__ __align__(16) bf16 BG2h[16384], BG2l[16384];   // inv height [m][j]
__device__ float g_mw[4096];

// ---------------- helpers ----------------
__device__ __forceinline__ void splitf(float v, bf16& h, bf16& l) {
    h = __float2bfloat16(v);
    l = __float2bfloat16(v - __bfloat162float(h));
}
__device__ __forceinline__ u32 pack_split(float v) {
    bf16 h, l; splitf(v, h, l);
    return (u32)__bfloat16_as_ushort(h) | ((u32)__bfloat16_as_ushort(l) << 16);
}
__device__ __forceinline__ void split_store2(bf16* H, bf16* L, size_t off, float a, float b) {
    bf16 ha, la, hb, lb; splitf(a, ha, la); splitf(b, hb, lb);
    *(__nv_bfloat162*)(H + off) = __halves2bfloat162(ha, hb);
    *(__nv_bfloat162*)(L + off) = __halves2bfloat162(la, lb);
}
__device__ __forceinline__ u32 prmtf(u32 a, u32 b, u32 s) {
    u32 d; asm("prmt.b32 %0,%1,%2,%3;" : "=r"(d) : "r"(a), "r"(b), "r"(s)); return d;
}
__device__ __forceinline__ float gelu_f(float v) {
    return 0.5f * v * (1.0f + erff(v * 0.70710678118654752f));
}

// ---------------- basis precompute (split planes) ----------------
__global__ void k_basis(const float* __restrict__ mwin) {
    int i = blockIdx.x * blockDim.x + threadIdx.x;
    const double PI2 = 6.283185307179586476925286766559;
    if (i < 16384) {
        int r = i >> 7, c = i & 127;
        float v = 0.f;
        if (r < 126) {
            int k = c & 63;
            double th = PI2 * (double)(k * r) / 126.0;
            v = (c < 64) ? (float)cos(th) : (float)(-sin(th));
        }
        splitf(v, BWh[i], BWl[i]);
        float v2 = 0.f;
        if (c < 126) {
            int k = r & 63;
            double a = (k == 0 || k == 63) ? (1.0 / 126.0) : (2.0 / 126.0);
            double th = PI2 * (double)(k * c) / 126.0;
            v2 = (r < 64) ? (float)(a * cos(th)) : (float)(-a * sin(th));
        }
        splitf(v2, BIh[i], BIl[i]);
        {
            int ky = r & 63, h = c & 63;
            double th = PI2 * (double)(ky * h) / 64.0;
            double cs = cos(th), sn = sin(th);
            float g = (float)((r < 64) ? ((c < 64) ? cs : sn) : ((c < 64) ? -sn : cs));
            splitf(g, BGh[i], BGl[i]);
        }
        {
            int h = r & 63, ky = c & 63;
            double th = PI2 * (double)(ky * h) / 64.0;
            double cs = cos(th) / 64.0, sn = sin(th) / 64.0;
            float g = (float)((r < 64) ? ((c < 64) ? cs : -sn) : ((c < 64) ? sn : cs));
            splitf(g, BG2h[i], BG2l[i]);
        }
    }
    if (i < 4096) {
        int ky = i >> 6, kx = i & 63;
        float s1 = 1.f / (1.f + expf(-mwin[i]));
        if (kx == 0 || kx == 63) {
            float s2 = 1.f / (1.f + expf(-mwin[(((64 - ky) & 63) << 6) + kx]));
            s1 = 0.5f * (s1 + s2);
        }
        g_mw[i] = s1;
    }
}

// ---------------- encoder 1x1 conv 3 -> 64 ----------------
__global__ __launch_bounds__(256) void k_enc(const float* __restrict__ xin,
                                             const float* __restrict__ ew,
                                             const float* __restrict__ eb) {
    __shared__ float sx[3 * 126];
    __shared__ float sw[192];
    __shared__ float sb[64];
    int b = blockIdx.x >> 6, h = blockIdx.x & 63;
    int t = threadIdx.x;
    if (t < 192) sw[t] = ew[t];
    if (t < 64)  sb[t] = eb[t];
    for (int idx = t; idx < 378; idx += 256) {
        int j = idx / 126, w = idx % 126;
        sx[idx] = xin[(size_t)(b * 3 + j) * HW_ + h * 126 + w];
    }
    __syncthreads();
    for (int idx = t; idx < 64 * 126; idx += 256) {
        int c = idx / 126, w = idx % 126;
        float v = sb[c] + sw[c * 3] * sx[w] + sw[c * 3 + 1] * sx[126 + w]
                        + sw[c * 3 + 2] * sx[252 + w];
        size_t off = (size_t)(b * 64 + c) * HWP_ + h * 128 + w;
        splitf(v, P0h[off], P0l[off]);
    }
}

// ======================================================================
// mma core: warp tile 32x32, split-bf16 (3 MMAs)
// ======================================================================
#define LDSM4(R0,R1,R2,R3,ADDR)                                              \
    asm volatile("ldmatrix.sync.aligned.m8n8.x4.shared.b16 {%0,%1,%2,%3}, [%4];" \
        : "=r"(R0),"=r"(R1),"=r"(R2),"=r"(R3) : "r"(ADDR))
#define LDSM4T(R0,R1,R2,R3,ADDR)                                             \
    asm volatile("ldmatrix.sync.aligned.m8n8.x4.trans.shared.b16 {%0,%1,%2,%3}, [%4];" \
        : "=r"(R0),"=r"(R1),"=r"(R2),"=r"(R3) : "r"(ADDR))
#define MMA16816(D,A,B)                                                      \
    asm volatile("mma.sync.aligned.m16n8k16.row.col.f32.bf16.bf16.f32 "      \
        "{%0,%1,%2,%3}, {%4,%5,%6,%7}, {%8,%9}, {%0,%1,%2,%3};"              \
        : "+f"((D)[0]),"+f"((D)[1]),"+f"((D)[2]),"+f"((D)[3])                \
        : "r"((A)[0]),"r"((A)[1]),"r"((A)[2]),"r"((A)[3]),                   \
          "r"((B)[0]),"r"((B)[1]))

template<int SA, int SB, int KSTEPS>
__device__ __forceinline__ void mma_core(
    const bf16* Ah, const bf16* Al, const bf16* Bh, const bf16* Bl,
    int m0w, int n0w, int lane, float (&acc)[2][4][4])
{
    unsigned baAh = (unsigned)__cvta_generic_to_shared(Ah);
    unsigned baAl = (unsigned)__cvta_generic_to_shared(Al);
    unsigned baBh = (unsigned)__cvta_generic_to_shared(Bh);
    unsigned baBl = (unsigned)__cvta_generic_to_shared(Bl);
    int aRow = m0w + (lane & 15);
    int aCol = (lane >> 4) << 3;
    int bRow = lane & 15;
    int bCol = n0w + ((lane >> 4) << 3);
#pragma unroll
    for (int ks = 0; ks < KSTEPS; ks++) {
        uint32_t ah[2][4], al[2][4], bh[4][2], bl[4][2];
#pragma unroll
        for (int mt = 0; mt < 2; mt++) {
            unsigned offA = (unsigned)((aRow + mt * 16) * SA + ks * 16 + aCol) * 2u;
            LDSM4(ah[mt][0], ah[mt][1], ah[mt][2], ah[mt][3], baAh + offA);
            LDSM4(al[mt][0], al[mt][1], al[mt][2], al[mt][3], baAl + offA);
        }
#pragma unroll
        for (int np = 0; np < 2; np++) {
            unsigned offB = (unsigned)((ks * 16 + bRow) * SB + bCol + np * 16) * 2u;
            LDSM4T(bh[2*np][0], bh[2*np][1], bh[2*np+1][0], bh[2*np+1][1], baBh + offB);
            LDSM4T(bl[2*np][0], bl[2*np][1], bl[2*np+1][0], bl[2*np+1][1], baBl + offB);
        }
#pragma unroll
        for (int mt = 0; mt < 2; mt++)
#pragma unroll
            for (int nt = 0; nt < 4; nt++) {
                MMA16816(acc[mt][nt], ah[mt], bh[nt]);
                MMA16816(acc[mt][nt], ah[mt], bl[nt]);
                MMA16816(acc[mt][nt], al[mt], bh[nt]);
            }
    }
}

#define XPLANE 9216            // max(64*136, 128*72)
#define YPLANE (128 * 136)
#define RACC _Pragma("unroll") for (int a_ = 0; a_ < 2; a_++)                \
    _Pragma("unroll") for (int b_ = 0; b_ < 4; b_++)                         \
    _Pragma("unroll") for (int c_ = 0; c_ < 4; c_++) acc[a_][b_][c_] = 0.f;

// copy helpers for staging
#define STAGE_Y(SRC_H, SRC_L)                                                \
    {                                                                        \
        const uint4* _h = (const uint4*)(SRC_H);                             \
        const uint4* _l = (const uint4*)(SRC_L);                             \
        for (int idx = t; idx < 2048; idx += 256) {                          \
            int r = idx >> 4, c = idx & 15;                                  \
            *(uint4*)(Yh + r * 136 + c * 8) = _h[idx];                       \
            *(uint4*)(Yl + r * 136 + c * 8) = _l[idx];                       \
        }                                                                    \
    }

// ======================================================================
// FUSED forward, 1 bc per CTA, 256 thr (8 warps): P0 -> p1
// ======================================================================
__global__ __launch_bounds__(256) void k_fwd_fused() {
    extern __shared__ __align__(16) char smraw[];
    bf16* Xh = (bf16*)smraw;
    bf16* Xl = Xh + XPLANE;
    bf16* Yh = Xl + XPLANE;
    bf16* Yl = Yh + YPLANE;
    int t = threadIdx.x, lane = t & 31, warp = t >> 5;
    int bc = blockIdx.x;

    const uint4* aH = (const uint4*)(P0h + (size_t)bc * HWP_);
    const uint4* aL = (const uint4*)(P0l + (size_t)bc * HWP_);
    for (int idx = t; idx < 1024; idx += 256) {
        int r = idx >> 4, c = idx & 15;
        *(uint4*)(Xh + r * 136 + c * 8) = aH[idx];
        *(uint4*)(Xl + r * 136 + c * 8) = aL[idx];
    }
    STAGE_Y(BWh, BWl)
    __syncthreads();

    int m0w1 = (warp >> 2) * 32, n0w1 = (warp & 3) * 32;
    float acc[2][4][4];
    RACC
    mma_core<136, 136, 8>(Xh, Xl, Yh, Yl, m0w1, n0w1, lane, acc);
    __syncthreads();

    STAGE_Y(BGh, BGl)
    {
        int rb = m0w1 + (lane >> 2), cb = n0w1 + (lane & 3) * 2;
#pragma unroll
        for (int mt = 0; mt < 2; mt++)
#pragma unroll
            for (int nt = 0; nt < 4; nt++) {
                int col = cb + nt * 8;
                int base = (col >> 6) * 64, c2 = col & 63;
                int r0 = rb + mt * 16, r1 = r0 + 8;
                split_store2(Xh, Xl, (size_t)(base + r0) * 72 + c2,
                             acc[mt][nt][0], acc[mt][nt][1]);
                split_store2(Xh, Xl, (size_t)(base + r1) * 72 + c2,
                             acc[mt][nt][2], acc[mt][nt][3]);
            }
    }
    __syncthreads();

    int m0w2 = (warp >> 1) * 32, n0w2 = (warp & 1) * 32;
    RACC
    mma_core<136, 72, 8>(Yh, Yl, Xh, Xl, m0w2, n0w2, lane, acc);

    int rb2 = m0w2 + (lane >> 2), cb2 = n0w2 + (lane & 3) * 2;
#pragma unroll
    for (int mt = 0; mt < 2; mt++)
#pragma unroll
        for (int nt = 0; nt < 4; nt++) {
            int kx = cb2 + nt * 8;
            int m0 = rb2 + mt * 16, m1 = m0 + 8;
            float2 w0 = *(const float2*)(g_mw + (m0 & 63) * 64 + kx);
            float2 w1 = *(const float2*)(g_mw + (m1 & 63) * 64 + kx);
            *(uint2*)(g_p1 + (size_t)bc * 8192 + m0 * 64 + kx) =
                make_uint2(pack_split(acc[mt][nt][0] * w0.x), pack_split(acc[mt][nt][1] * w0.y));
            *(uint2*)(g_p1 + (size_t)bc * 8192 + m1 * 64 + kx) =
                make_uint2(pack_split(acc[mt][nt][2] * w1.x), pack_split(acc[mt][nt][3] * w1.y));
        }
}

// ======================================================================
// FUSED inverse (final layer), 1 bc per CTA: p1 -> P0 (bias+GELU)
// ======================================================================
__global__ __launch_bounds__(256) void k_inv_fused(const float* __restrict__ sb,
                                                   const float* __restrict__ mb_) {
    extern __shared__ __align__(16) char smraw[];
    bf16* Xh = (bf16*)smraw;
    bf16* Xl = Xh + XPLANE;
    bf16* Yh = Xl + XPLANE;
    bf16* Yl = Yh + YPLANE;
    int t = threadIdx.x, lane = t & 31, warp = t >> 5;
    int bc = blockIdx.x;

    STAGE_Y(BG2h, BG2l)
    const u32* src = g_p1 + (size_t)bc * 8192;
    for (int idx = t; idx < 4096; idx += 256) {
        int r = idx >> 5, pc = idx & 31;
        int col0 = pc * 2;
        uint2 p = *(const uint2*)(src + r * 64 + col0);
        *(u32*)(Xh + r * 72 + col0) = prmtf(p.x, p.y, 0x5410);
        *(u32*)(Xl + r * 72 + col0) = prmtf(p.x, p.y, 0x7632);
    }
    __syncthreads();

    int m0w1 = (warp >> 1) * 32, n0w1 = (warp & 1) * 32;
    float acc[2][4][4];
    RACC
    mma_core<136, 72, 8>(Yh, Yl, Xh, Xl, m0w1, n0w1, lane, acc);
    __syncthreads();

    STAGE_Y(BIh, BIl)
    {
        int rb = m0w1 + (lane >> 2), cb = n0w1 + (lane & 3) * 2;
#pragma unroll
        for (int mt = 0; mt < 2; mt++)
#pragma unroll
            for (int nt = 0; nt < 4; nt++) {
                int kx = cb + nt * 8;
                int r0 = rb + mt * 16, r1 = r0 + 8;
                split_store2(Xh, Xl, (size_t)(r0 & 63) * 136 + (r0 >> 6) * 64 + kx,
                             acc[mt][nt][0], acc[mt][nt][1]);
                split_store2(Xh, Xl, (size_t)(r1 & 63) * 136 + (r1 >> 6) * 64 + kx,
                             acc[mt][nt][2], acc[mt][nt][3]);
            }
    }
    __syncthreads();

    int m0w2 = (warp >> 2) * 32, n0w2 = (warp & 3) * 32;
    RACC
    mma_core<136, 136, 8>(Xh, Xl, Yh, Yl, m0w2, n0w2, lane, acc);

    int ch = bc & 63;
    float bias = __ldg(sb + ch) + __ldg(mb_ + ch);
    int rb2 = m0w2 + (lane >> 2), cb2 = n0w2 + (lane & 3) * 2;
#pragma unroll
    for (int mt = 0; mt < 2; mt++)
#pragma unroll
        for (int nt = 0; nt < 4; nt++) {
            int w = cb2 + nt * 8;
            if (w >= 126) continue;
            int h0 = rb2 + mt * 16, h1 = h0 + 8;
            split_store2(P0h, P0l, (size_t)bc * HWP_ + h0 * 128 + w,
                         gelu_f(acc[mt][nt][0] + bias), gelu_f(acc[mt][nt][1] + bias));
            split_store2(P0h, P0l, (size_t)bc * HWP_ + h1 * 128 + w,
                         gelu_f(acc[mt][nt][2] + bias), gelu_f(acc[mt][nt][3] + bias));
        }
}

// ======================================================================
// COMBO: inverse(l) + GELU + forward(l+1), all in smem: p1 -> p1 (in place)
// 4 MMA phases. GELU values at w=126/127 are harmless: BW rows >=126 are zero.
// ======================================================================
__global__ __launch_bounds__(256) void k_combo(const float* __restrict__ sb,
                                               const float* __restrict__ mb_) {
    extern __shared__ __align__(16) char smraw[];
    bf16* Xh = (bf16*)smraw;
    bf16* Xl = Xh + XPLANE;
    bf16* Yh = Xl + XPLANE;
    bf16* Yl = Yh + YPLANE;
    int t = threadIdx.x, lane = t & 31, warp = t >> 5;
    int bc = blockIdx.x;

    // ---- inv phase 1: C2'[(ri2,h)][kx] = BG2 * unpack(p1[bc]) ----
    STAGE_Y(BG2h, BG2l)
    const u32* src = g_p1 + (size_t)bc * 8192;
    for (int idx = t; idx < 4096; idx += 256) {
        int r = idx >> 5, pc = idx & 31;
        int col0 = pc * 2;
        uint2 p = *(const uint2*)(src + r * 64 + col0);
        *(u32*)(Xh + r * 72 + col0) = prmtf(p.x, p.y, 0x5410);
        *(u32*)(Xl + r * 72 + col0) = prmtf(p.x, p.y, 0x7632);
    }
    __syncthreads();

    int m0n = (warp >> 1) * 32, n0n = (warp & 1) * 32;   // narrow: 128x64
    int m0wd = (warp >> 2) * 32, n0wd = (warp & 3) * 32; // wide:   64x128
    float acc[2][4][4];
    RACC
    mma_core<136, 72, 8>(Yh, Yl, Xh, Xl, m0n, n0n, lane, acc);
    __syncthreads();

    // ---- restage Y <- BI; transpose C2' -> X [64][136] ----
    STAGE_Y(BIh, BIl)
    {
        int rb = m0n + (lane >> 2), cb = n0n + (lane & 3) * 2;
#pragma unroll
        for (int mt = 0; mt < 2; mt++)
#pragma unroll
            for (int nt = 0; nt < 4; nt++) {
                int kx = cb + nt * 8;
                int r0 = rb + mt * 16, r1 = r0 + 8;
                split_store2(Xh, Xl, (size_t)(r0 & 63) * 136 + (r0 >> 6) * 64 + kx,
                             acc[mt][nt][0], acc[mt][nt][1]);
                split_store2(Xh, Xl, (size_t)(r1 & 63) * 136 + (r1 >> 6) * 64 + kx,
                             acc[mt][nt][2], acc[mt][nt][3]);
            }
    }
    __syncthreads();

    // ---- inv phase 2: C3[h][w] = X * BI ----
    RACC
    mma_core<136, 136, 8>(Xh, Xl, Yh, Yl, m0wd, n0wd, lane, acc);
    __syncthreads();   // all reads of X/Y complete

    // ---- GELU -> X [64][136]; restage Y <- BW ----
    int ch = bc & 63;
    float bias = __ldg(sb + ch) + __ldg(mb_ + ch);
    {
        int rb = m0wd + (lane >> 2), cb = n0wd + (lane & 3) * 2;
#pragma unroll
        for (int mt = 0; mt < 2; mt++)
#pragma unroll
            for (int nt = 0; nt < 4; nt++) {
                int w = cb + nt * 8;
                int h0 = rb + mt * 16, h1 = h0 + 8;
                split_store2(Xh, Xl, (size_t)h0 * 136 + w,
                             gelu_f(acc[mt][nt][0] + bias), gelu_f(acc[mt][nt][1] + bias));
                split_store2(Xh, Xl, (size_t)h1 * 136 + w,
                             gelu_f(acc[mt][nt][2] + bias), gelu_f(acc[mt][nt][3] + bias));
            }
    }
    STAGE_Y(BWh, BWl)
    __syncthreads();

    // ---- fwd phase 1: C1[h][n] = X * BW ----
    RACC
    mma_core<136, 136, 8>(Xh, Xl, Yh, Yl, m0wd, n0wd, lane, acc);
    __syncthreads();

    // ---- restage Y <- BG; transpose C1 -> X [128][72] ----
    STAGE_Y(BGh, BGl)
    {
        int rb = m0wd + (lane >> 2), cb = n0wd + (lane & 3) * 2;
#pragma unroll
        for (int mt = 0; mt < 2; mt++)
#pragma unroll
            for (int nt = 0; nt < 4; nt++) {
                int col = cb + nt * 8;
                int base = (col >> 6) * 64, c2 = col & 63;
                int r0 = rb + mt * 16, r1 = r0 + 8;
                split_store2(Xh, Xl, (size_t)(base + r0) * 72 + c2,
                             acc[mt][nt][0], acc[mt][nt][1]);
                split_store2(Xh, Xl, (size_t)(base + r1) * 72 + c2,
                             acc[mt][nt][2], acc[mt][nt][3]);
            }
    }
    __syncthreads();

    // ---- fwd phase 2: C2[(ri,ky)][kx] = BG * X ----
    RACC
    mma_core<136, 72, 8>(Yh, Yl, Xh, Xl, m0n, n0n, lane, acc);

    // ---- epilogue: *mw -> p1[bc] (in place; own slice fully consumed) ----
    int rb2 = m0n + (lane >> 2), cb2 = n0n + (lane & 3) * 2;
#pragma unroll
    for (int mt = 0; mt < 2; mt++)
#pragma unroll
        for (int nt = 0; nt < 4; nt++) {
            int kx = cb2 + nt * 8;
            int m0 = rb2 + mt * 16, m1 = m0 + 8;
            float2 w0 = *(const float2*)(g_mw + (m0 & 63) * 64 + kx);
            float2 w1 = *(const float2*)(g_mw + (m1 & 63) * 64 + kx);
            *(uint2*)(g_p1 + (size_t)bc * 8192 + m0 * 64 + kx) =
                make_uint2(pack_split(acc[mt][nt][0] * w0.x), pack_split(acc[mt][nt][1] * w0.y));
            *(uint2*)(g_p1 + (size_t)bc * 8192 + m1 * 64 + kx) =
                make_uint2(pack_split(acc[mt][nt][2] * w1.x), pack_split(acc[mt][nt][3] * w1.y));
        }
}

// ---------------- transpose to mode-major (packed u32) ----------------
__global__ __launch_bounds__(256) void k_t1() {
    __shared__ u32 s[128 * 65];
    int b = blockIdx.x >> 6, ky = blockIdx.x & 63;
    int t = threadIdx.x;
    for (int idx = t; idx < 8192; idx += 256) {
        int i = idx >> 7, r = idx & 127, ri = r >> 6, kx = r & 63;
        s[(ri * 64 + i) * 65 + kx] =
            g_p1[(size_t)(b * 64 + i) * 8192 + ri * 4096 + ky * 64 + kx];
    }
    __syncthreads();
    for (int idx = t; idx < 8192; idx += 256) {
        int kx = idx >> 7, c = idx & 127;
        g_p2[(size_t)(ky * 64 + kx) * 16384 + b * 128 + c] = s[c * 65 + kx];
    }
}

// ---------------- transpose back from mode-major (packed u32) ----------------
__global__ __launch_bounds__(256) void k_t2() {
    __shared__ u32 s[128 * 65];
    int b = blockIdx.x >> 6, ky = blockIdx.x & 63;
    int t = threadIdx.x;
    for (int idx = t; idx < 8192; idx += 256) {
        int kx = idx >> 7, c = idx & 127;
        s[c * 65 + kx] = g_p3[(size_t)(ky * 64 + kx) * 16384 + b * 128 + c];
    }
    __syncthreads();
    for (int idx = t; idx < 8192; idx += 256) {
        int o = idx >> 7, r = idx & 127, ri = r >> 6, kx = r & 63;
        g_p1[(size_t)(b * 64 + o) * 8192 + ri * 4096 + ky * 64 + kx] =
            s[(ri * 64 + o) * 65 + kx];
    }
}

// ---------------- weight fold (writes split planes) ----------------
__global__ void k_wt(const float* __restrict__ spec, const float* __restrict__ mlp) {
    __shared__ float tile[32][33];
    int x = blockIdx.x * 32 + threadIdx.x;   // mode
    int yb = blockIdx.y * 32;                // io
#pragma unroll
    for (int j = 0; j < 32; j += 8)
        tile[threadIdx.y + j][threadIdx.x] = spec[(size_t)(yb + threadIdx.y + j) * 4096 + x];
    __syncthreads();
    int io2 = yb + threadIdx.x;
    float madd = mlp[(io2 & 63) * 64 + (io2 >> 6)];
    int mb = blockIdx.x * 32;
#pragma unroll
    for (int j = 0; j < 32; j += 8) {
        float v = tile[threadIdx.x][threadIdx.y + j] + madd;
        size_t off = (size_t)(mb + threadIdx.y + j) * 4096 + io2;
        splitf(v, WTh[off], WTl[off]);
    }
}

// ======================================================================
// per-mode GEMM: C[256 x 64] = X[256 x 64] W[64 x 64], K=64
// ======================================================================
__global__ __launch_bounds__(512) void k_sgemm() {
    extern __shared__ __align__(16) char smraw[];
    bf16* Ah = (bf16*)smraw;            // [256][72]
    bf16* Al = Ah + 256 * 72;
    bf16* Bh = Al + 256 * 72;           // [64][72]
    bf16* Bl = Bh + 64 * 72;
    int t = threadIdx.x, lane = t & 31, warp = t >> 5;
    int mode = blockIdx.x;
    const u32* asrc = g_p2 + (size_t)mode * 16384;
    for (int idx = t; idx < 8192; idx += 512) {
        int r = idx >> 5, pc = idx & 31;
        int col0 = pc * 2;
        uint2 p = *(const uint2*)(asrc + r * 64 + col0);
        *(u32*)(Ah + r * 72 + col0) = prmtf(p.x, p.y, 0x5410);
        *(u32*)(Al + r * 72 + col0) = prmtf(p.x, p.y, 0x7632);
    }
    const uint4* sBh = (const uint4*)(WTh + (size_t)mode * 4096);
    const uint4* sBl = (const uint4*)(WTl + (size_t)mode * 4096);
    for (int idx = t; idx < 512; idx += 512) {
        int r = idx >> 3, c = idx & 7;
        *(uint4*)(Bh + r * 72 + c * 8) = sBh[idx];
        *(uint4*)(Bl + r * 72 + c * 8) = sBl[idx];
    }
    __syncthreads();
    int m0w = (warp >> 1) * 32, n0w = (warp & 1) * 32;
    float acc[2][4][4];
    RACC
    mma_core<72, 72, 4>(Ah, Al, Bh, Bl, m0w, n0w, lane, acc);
    int rb = m0w + (lane >> 2), cb = n0w + (lane & 3) * 2;
    u32* dst = g_p3 + (size_t)mode * 16384;
#pragma unroll
    for (int mt = 0; mt < 2; mt++)
#pragma unroll
        for (int nt = 0; nt < 4; nt++) {
            int col = cb + nt * 8;
            int r0 = rb + mt * 16, r1 = r0 + 8;
            *(uint2*)(dst + r0 * 64 + col) =
                make_uint2(pack_split(acc[mt][nt][0]), pack_split(acc[mt][nt][1]));
            *(uint2*)(dst + r1 * 64 + col) =
                make_uint2(pack_split(acc[mt][nt][2]), pack_split(acc[mt][nt][3]));
        }
}

// ---------------- decoder 1x1 conv 64 -> 1 ----------------
__global__ __launch_bounds__(256) void k_dec(const float* __restrict__ dw,
                                             const float* __restrict__ db,
                                             float* __restrict__ out) {
    __shared__ float sw[64];
    int b = blockIdx.x, t = threadIdx.x;
    if (t < 64) sw[t] = dw[t];
    __syncthreads();
    float bias = __ldg(db);
    for (int p = t; p < HWP_; p += 256) {
        int w = p & 127;
        if (w >= 126) continue;
        int h = p >> 7;
        float s = bias;
        size_t base = (size_t)b * 64 * HWP_ + p;
#pragma unroll 8
        for (int c = 0; c < 64; c++) {
            size_t off = base + (size_t)c * HWP_;
            s = fmaf(sw[c], __bfloat162float(P0h[off]) + __bfloat162float(P0l[off]), s);
        }
        out[(size_t)b * HW_ + h * 126 + w] = s;
    }
}

extern "C" void kernel_launch(void* const* d_in, const int* in_sizes, int n_in,
                              void* d_out, int out_size) {
    const float* x       = (const float*)d_in[0];
    const float* mode_w  = (const float*)d_in[1];
    const float* enc_w   = (const float*)d_in[2];
    const float* enc_b   = (const float*)d_in[3];
    const float* dec_w   = (const float*)d_in[4];
    const float* dec_b   = (const float*)d_in[5];
    const float* spec_w  = (const float*)d_in[6];
    const float* spec_b  = (const float*)d_in[7];
    const float* mlp_w   = (const float*)d_in[8];
    const float* mlp_b   = (const float*)d_in[9];
    float* out = (float*)d_out;

    const int smemF = (2 * XPLANE + 2 * YPLANE) * 2;          // 106,496 B -> 2 CTA/SM
    const int smemS = (2 * 256 * 72 + 2 * 64 * 72) * 2;       //  92,160 B
    cudaFuncSetAttribute(k_fwd_fused, cudaFuncAttributeMaxDynamicSharedMemorySize, smemF);
    cudaFuncSetAttribute(k_inv_fused, cudaFuncAttributeMaxDynamicSharedMemorySize, smemF);
    cudaFuncSetAttribute(k_combo,     cudaFuncAttributeMaxDynamicSharedMemorySize, smemF);
    cudaFuncSetAttribute(k_sgemm,     cudaFuncAttributeMaxDynamicSharedMemorySize, smemS);

    k_basis<<<64, 256>>>(mode_w);
    k_enc<<<8192, 256>>>(x, enc_w, enc_b);

    k_wt<<<dim3(128, 128), dim3(32, 8)>>>(spec_w, mlp_w);
    k_fwd_fused<<<8192, 256, smemF>>>();

    for (int l = 0; l < 4; l++) {
        k_t1<<<8192, 256>>>();
        k_sgemm<<<4096, 512, smemS>>>();
        k_t2<<<8192, 256>>>();
        if (l < 3) {
            k_wt<<<dim3(128, 128), dim3(32, 8)>>>(spec_w + (size_t)(l + 1) * 16777216,
                                                  mlp_w + (size_t)(l + 1) * 4096);
            k_combo<<<8192, 256, smemF>>>(spec_b + l * 64, mlp_b + l * 64);
        } else {
            k_inv_fused<<<8192, 256, smemF>>>(spec_b + l * 64, mlp_b + l * 64);
        }
    }
    k_dec<<<128, 256>>>(dec_w, dec_b, out);
}